// round 9
// baseline (speedup 1.0000x reference)
#include <cuda_runtime.h>
#include <cstdint>

#define BATCH 16
#define NNODE 1024
#define DIM 256
#define HEADS 4
#define NBR 1023
#define TSTEPS 20

// ---------------- scratch (device globals; no allocation allowed) ----------------
__device__ float g_h0[BATCH * NNODE * DIM];
__device__ float g_h1[BATCH * NNODE * DIM];
__device__ float g_wh[BATCH * NNODE * DIM];
__device__ float g_pos[BATCH * NNODE * 2];
__device__ float g_as[BATCH * HEADS * NNODE];
__device__ float g_ad[BATCH * HEADS * NNODE];
__device__ uint32_t g_asmaxu[2 * BATCH * HEADS];  // [layer][bh], order-preserving uint enc
__device__ uint32_t g_adjT[BATCH * 32 * NNODE];   // [b][jword][i] bit lane = j%32

// ======================= helpers =======================
__device__ __forceinline__ uint32_t tf32r(float x) {
    uint32_t r;
    asm("cvt.rna.tf32.f32 %0, %1;" : "=r"(r) : "f"(x));
    return r;
}
__device__ __forceinline__ void mma_tf32(float* c, uint32_t a0, uint32_t a1,
                                         uint32_t a2, uint32_t a3,
                                         uint32_t b0, uint32_t b1) {
    asm volatile(
        "mma.sync.aligned.m16n8k8.row.col.f32.tf32.tf32.f32 "
        "{%0,%1,%2,%3}, {%4,%5,%6,%7}, {%8,%9}, {%0,%1,%2,%3};"
        : "+f"(c[0]), "+f"(c[1]), "+f"(c[2]), "+f"(c[3])
        : "r"(a0), "r"(a1), "r"(a2), "r"(a3), "r"(b0), "r"(b1));
}
__device__ __forceinline__ float slctf(float a, float b, float c) {
    float d;
    asm("slct.f32.f32 %0, %1, %2, %3;" : "=f"(d) : "f"(a), "f"(b), "f"(c));
    return d;
}
__device__ __forceinline__ uint32_t fenc(float f) {
    uint32_t b = __float_as_uint(f);
    return ((int)b < 0) ? ~b : (b | 0x80000000u);
}
__device__ __forceinline__ float fdec(uint32_t u) {
    return __uint_as_float((u & 0x80000000u) ? (u ^ 0x80000000u) : ~u);
}

// ---------------- embed: 8 nodes per block, weight col in regs ----------------
__global__ __launch_bounds__(256) void embed_kernel(
    const float* __restrict__ ego, const float* __restrict__ nbr,
    const float* __restrict__ node_w, const float* __restrict__ node_b,
    const float* __restrict__ node_g, const float* __restrict__ node_bb,
    const float* __restrict__ ego_w, const float* __restrict__ ego_b,
    const float* __restrict__ ego_g, const float* __restrict__ ego_bb)
{
    int t = threadIdx.x;
    int bn0 = blockIdx.x * 8;
    __shared__ float f[8][5];
    __shared__ float ws[8][8], wq[8][8];
    if (t < 40) {
        int nn = t / 5, k = t - nn * 5;
        int bn = bn0 + nn;
        int b = bn >> 10, n = bn & 1023;
        float v = (n == 0) ? ego[(b * TSTEPS + TSTEPS - 1) * 7 + k]
                           : nbr[((b * NBR + (n - 1)) * TSTEPS + TSTEPS - 1) * 11 + k];
        f[nn][k] = v;
        if (k < 2) g_pos[bn * 2 + k] = v;
    }
    __syncthreads();
    float wn[5];
#pragma unroll
    for (int k = 0; k < 5; k++) wn[k] = node_w[k * DIM + t];
    float nb = node_b[t];
    int lane = t & 31, w = t >> 5;
    float vv[8];
#pragma unroll
    for (int nn = 0; nn < 8; nn++) {
        int n = (bn0 + nn) & 1023;
        float v;
        if (n == 0) {
            v = ego_b[t];
#pragma unroll
            for (int k = 0; k < 5; k++) v = fmaf(f[nn][k], ego_w[k * DIM + t], v);
        } else {
            v = nb;
#pragma unroll
            for (int k = 0; k < 5; k++) v = fmaf(f[nn][k], wn[k], v);
        }
        v = fmaxf(v, 0.f);
        vv[nn] = v;
        float s = v, q = v * v;
#pragma unroll
        for (int o = 16; o; o >>= 1) {
            s += __shfl_down_sync(0xffffffffu, s, o);
            q += __shfl_down_sync(0xffffffffu, q, o);
        }
        if (lane == 0) { ws[nn][w] = s; wq[nn][w] = q; }
    }
    __syncthreads();
    float ng = node_g[t], nbb = node_bb[t];
#pragma unroll
    for (int nn = 0; nn < 8; nn++) {
        int bn = bn0 + nn;
        int n = bn & 1023;
        float sum = 0.f, sq = 0.f;
#pragma unroll
        for (int i = 0; i < 8; i++) { sum += ws[nn][i]; sq += wq[nn][i]; }
        float mean = sum * (1.f / 256.f);
        float var = fmaxf(sq * (1.f / 256.f) - mean * mean, 0.f);
        float inv = rsqrtf(var + 1e-5f);
        float gg = ng, bb2 = nbb;
        if (n == 0) { gg = ego_g[t]; bb2 = ego_bb[t]; }
        g_h0[(size_t)bn * DIM + t] = (vv[nn] - mean) * inv * gg + bb2;
    }
}

// ---------------- adjacency bitmask + asmax buffer init ----------------
__global__ __launch_bounds__(256) void adj_kernel()
{
    int b = blockIdx.z, jw = blockIdx.y;
    int lane = threadIdx.x & 31, w = threadIdx.x >> 5;
    if (blockIdx.x == 0 && jw == 0 && threadIdx.x < 8) {
        int l = threadIdx.x >> 2, h = threadIdx.x & 3;
        g_asmaxu[l * (BATCH * HEADS) + b * HEADS + h] = 0u;
    }
    int j = jw * 32 + lane;
    float2 pj = ((const float2*)g_pos)[b * NNODE + j];
    int i0 = blockIdx.x * 32 + w;
#pragma unroll
    for (int q = 0; q < 4; q++) {
        int i = i0 + q * 8;
        float2 pi = ((const float2*)g_pos)[b * NNODE + i];
        float dx = pj.x - pi.x, dy = pj.y - pi.y;
        bool a = (fmaf(dx, dx, dy * dy) < 2500.f) || (i == j);
        uint32_t word = __ballot_sync(0xffffffffu, a);
        if (lane == 0) g_adjT[(b * 32 + jw) * NNODE + i] = word;
    }
}

// ---------------- tf32 tensor-core GEMM (+fused a_src/a_dst + asmax) ----------
#define GA_STRIDE 36
#define GB_STRIDE 72
template <bool BIAS, bool SAD>
__global__ __launch_bounds__(256) void tgemm256(
    const float* __restrict__ A, const float* __restrict__ W,
    const float* __restrict__ bias, float* __restrict__ C,
    const float* __restrict__ asrc, const float* __restrict__ adst,
    int sadLayer)
{
    __shared__ float As[128 * GA_STRIDE];
    __shared__ float Bs[32 * GB_STRIDE];
    int tid = threadIdx.x, w = tid >> 5, lane = tid & 31;
    int g4 = lane >> 2, q4 = lane & 3;
    int m0 = blockIdx.x * 128, n0 = blockIdx.y * 64;
    int wm = w & 3, wn = w >> 2;
    int r0 = wm * 32, c0 = wn * 32;

    int af4 = tid & 7, arow = tid >> 3;
    int bf4 = tid & 15, brow = tid >> 4;
    const float* Ag = A + (size_t)(m0 + arow) * 256 + af4 * 4;
    const float* Wg = W + (size_t)brow * 256 + n0 + bf4 * 4;

    float acc[2][4][4];
#pragma unroll
    for (int mt = 0; mt < 2; mt++)
#pragma unroll
        for (int nt = 0; nt < 4; nt++)
#pragma unroll
            for (int k = 0; k < 4; k++) acc[mt][nt][k] = 0.f;

    float4 pa[4], pb[2];
#pragma unroll
    for (int q = 0; q < 4; q++) pa[q] = *(const float4*)(Ag + (size_t)q * 32 * 256);
#pragma unroll
    for (int q = 0; q < 2; q++) pb[q] = *(const float4*)(Wg + (size_t)q * 16 * 256);

    for (int kc = 0; kc < 8; kc++) {
        __syncthreads();
#pragma unroll
        for (int q = 0; q < 4; q++) {
            float* d = As + (arow + q * 32) * GA_STRIDE + af4 * 4;
            d[0] = __uint_as_float(tf32r(pa[q].x));
            d[1] = __uint_as_float(tf32r(pa[q].y));
            d[2] = __uint_as_float(tf32r(pa[q].z));
            d[3] = __uint_as_float(tf32r(pa[q].w));
        }
#pragma unroll
        for (int q = 0; q < 2; q++) {
            float* d = Bs + (brow + q * 16) * GB_STRIDE + bf4 * 4;
            d[0] = __uint_as_float(tf32r(pb[q].x));
            d[1] = __uint_as_float(tf32r(pb[q].y));
            d[2] = __uint_as_float(tf32r(pb[q].z));
            d[3] = __uint_as_float(tf32r(pb[q].w));
        }
        __syncthreads();
        if (kc < 7) {
            const float* Agn = Ag + (kc + 1) * 32;
            const float* Wgn = Wg + (size_t)(kc + 1) * 32 * 256;
#pragma unroll
            for (int q = 0; q < 4; q++) pa[q] = *(const float4*)(Agn + (size_t)q * 32 * 256);
#pragma unroll
            for (int q = 0; q < 2; q++) pb[q] = *(const float4*)(Wgn + (size_t)q * 16 * 256);
        }
#pragma unroll
        for (int kb = 0; kb < 4; kb++) {
            int k8 = kb * 8;
            const float* a0p = As + (r0 + g4) * GA_STRIDE + k8 + q4;
            uint32_t a00 = __float_as_uint(a0p[0]);
            uint32_t a01 = __float_as_uint(a0p[8 * GA_STRIDE]);
            uint32_t a02 = __float_as_uint(a0p[4]);
            uint32_t a03 = __float_as_uint(a0p[8 * GA_STRIDE + 4]);
            uint32_t a10 = __float_as_uint(a0p[16 * GA_STRIDE]);
            uint32_t a11 = __float_as_uint(a0p[24 * GA_STRIDE]);
            uint32_t a12 = __float_as_uint(a0p[16 * GA_STRIDE + 4]);
            uint32_t a13 = __float_as_uint(a0p[24 * GA_STRIDE + 4]);
            const float* bp = Bs + (k8 + q4) * GB_STRIDE + c0 + g4;
#pragma unroll
            for (int nt = 0; nt < 4; nt++) {
                uint32_t b0 = __float_as_uint(bp[nt * 8]);
                uint32_t b1 = __float_as_uint(bp[nt * 8 + 4 * GB_STRIDE]);
                mma_tf32(acc[0][nt], a00, a01, a02, a03, b0, b1);
                mma_tf32(acc[1][nt], a10, a11, a12, a13, b0, b1);
            }
        }
    }
    // ---- C store ----
#pragma unroll
    for (int mt = 0; mt < 2; mt++) {
        int row = m0 + r0 + mt * 16 + g4;
        float* c0p = C + (size_t)row * 256 + n0 + c0;
        float* c1p = c0p + 8 * 256;
#pragma unroll
        for (int nt = 0; nt < 4; nt++) {
            int cc = nt * 8 + q4 * 2;
            float bx = 0.f, by = 0.f;
            if (BIAS) { bx = bias[n0 + c0 + cc]; by = bias[n0 + c0 + cc + 1]; }
            float2 u0, u1;
            u0.x = acc[mt][nt][0] + bx; u0.y = acc[mt][nt][1] + by;
            u1.x = acc[mt][nt][2] + bx; u1.y = acc[mt][nt][3] + by;
            *(float2*)(c0p + cc) = u0;
            *(float2*)(c1p + cc) = u1;
        }
    }
    // ---- fused a_src / a_dst + asmax (block covers one full head's 64 cols) ----
    if (SAD) {
        float as_c[8], ad_c[8];
#pragma unroll
        for (int nt = 0; nt < 4; nt++) {
            int cg = n0 + c0 + nt * 8 + q4 * 2;
            as_c[nt * 2] = asrc[cg]; as_c[nt * 2 + 1] = asrc[cg + 1];
            ad_c[nt * 2] = adst[cg]; ad_c[nt * 2 + 1] = adst[cg + 1];
        }
        __syncthreads();                 // As no longer read; reuse as reduction buffer
        float* red = As;
#pragma unroll
        for (int mt = 0; mt < 2; mt++) {
            float sAs = 0.f, sAd = 0.f, sBs = 0.f, sBd = 0.f;
#pragma unroll
            for (int nt = 0; nt < 4; nt++) {
                sAs += acc[mt][nt][0] * as_c[nt * 2] + acc[mt][nt][1] * as_c[nt * 2 + 1];
                sBs += acc[mt][nt][2] * as_c[nt * 2] + acc[mt][nt][3] * as_c[nt * 2 + 1];
                sAd += acc[mt][nt][0] * ad_c[nt * 2] + acc[mt][nt][1] * ad_c[nt * 2 + 1];
                sBd += acc[mt][nt][2] * ad_c[nt * 2] + acc[mt][nt][3] * ad_c[nt * 2 + 1];
            }
#pragma unroll
            for (int o = 1; o < 4; o <<= 1) {
                sAs += __shfl_xor_sync(0xffffffffu, sAs, o);
                sAd += __shfl_xor_sync(0xffffffffu, sAd, o);
                sBs += __shfl_xor_sync(0xffffffffu, sBs, o);
                sBd += __shfl_xor_sync(0xffffffffu, sBd, o);
            }
            if (q4 == 0) {
                int rA = r0 + mt * 16 + g4, rB = rA + 8;
                *(float2*)&red[(rA * 2 + wn) * 2] = make_float2(sAs, sAd);
                *(float2*)&red[(rB * 2 + wn) * 2] = make_float2(sBs, sBd);
            }
        }
        __syncthreads();
        if (tid < 128) {
            float2 v0 = *(float2*)&red[(tid * 2 + 0) * 2];
            float2 v1 = *(float2*)&red[(tid * 2 + 1) * 2];
            int b = m0 >> 10, n = (m0 & 1023) + tid;
            int bh = b * HEADS + blockIdx.y;
            float asv = v0.x + v1.x;
            g_as[bh * NNODE + n] = asv;
            g_ad[bh * NNODE + n] = v0.y + v1.y;
            float m = asv;
#pragma unroll
            for (int o = 16; o; o >>= 1)
                m = fmaxf(m, __shfl_xor_sync(0xffffffffu, m, o));
            if (lane == 0)
                atomicMax(&g_asmaxu[sadLayer * (BATCH * HEADS) + bh], fenc(m));
        }
    }
}

// ---------------- GAT attention: 256 rows/block, register-P tf32 mma.sync ----------
// v2 fragment-major V layout: v2[j][g4][slot], slot stride 12 (slots 0..7 = nt, 8 = ones)
#define V2S 96
__global__ __launch_bounds__(256, 2) void gat_attn_mma(
    const float* __restrict__ wh, const float* __restrict__ gbias,
    float* __restrict__ hout, int layer)
{
    __shared__ __align__(16) float v2[64 * V2S];
    __shared__ float4 je[64];            // (as_j, E1_j, E2_j, -)
    __shared__ uint32_t adj_sm[512];

    int tid = threadIdx.x, w = tid >> 5, lane = tid & 31;
    int g4 = lane >> 2, q4 = lane & 3;
    int it = blockIdx.x, hh = blockIdx.y, b = blockIdx.z;
    int i0 = it * 256, bh = b * HEADS + hh;
    int r0 = w * 32;

    float F1[4], F2[4], adreg[4];
    {
        float mx = fdec(g_asmaxu[layer * (BATCH * HEADS) + bh]);
#pragma unroll
        for (int t = 0; t < 4; t++) {
            float ad = g_ad[bh * NNODE + i0 + r0 + t * 8 + g4];
            adreg[t] = ad;
            float mm = mx + ad;
            float mr = fmaxf(mm, 0.2f * mm);
            F1[t] = __expf(ad - mr);
            F2[t] = __expf(0.2f * ad - mr);
        }
    }
    // ones in slot 8 for every (j, g4): D cols 64..71 all become Z
#pragma unroll
    for (int q = 0; q < 2; q++) {
        int idx = q * 256 + tid;
        int jr = idx >> 3, gg = idx & 7;
        v2[jr * V2S + gg * 12 + 8] = 1.f;
    }

    float acc[2][9][4];
#pragma unroll
    for (int mt = 0; mt < 2; mt++)
#pragma unroll
        for (int n = 0; n < 9; n++)
#pragma unroll
            for (int k = 0; k < 4; k++) acc[mt][n][k] = 0.f;

    const float* whb = wh + ((size_t)(b * NNODE)) * DIM + hh * 64;
    const uint32_t* adjb = g_adjT + (size_t)b * 32 * NNODE + i0;

    for (int ch = 0; ch < 16; ch++) {
        int j0 = ch * 64;
        __syncthreads();
        // V chunk [64 x 64] -> v2 fragment-major (tf32-rounded)
#pragma unroll
        for (int q = 0; q < 4; q++) {
            int idx = q * 256 + tid;
            int jr = idx >> 4;
            int cbase = (idx & 15) * 4;
            float4 v = *(const float4*)(whb + (size_t)(j0 + jr) * DIM + cbase);
            int nt = cbase >> 3, gg = cbase & 7;
            float* dst = v2 + jr * V2S + nt;
            dst[(gg + 0) * 12] = __uint_as_float(tf32r(v.x));
            dst[(gg + 1) * 12] = __uint_as_float(tf32r(v.y));
            dst[(gg + 2) * 12] = __uint_as_float(tf32r(v.z));
            dst[(gg + 3) * 12] = __uint_as_float(tf32r(v.w));
        }
        if (tid < 64) {
            float a = g_as[bh * NNODE + j0 + tid];
            je[tid] = make_float4(a, __expf(a), __expf(0.2f * a), 0.f);
        }
        adj_sm[tid] = adjb[(size_t)(2 * ch) * NNODE + tid];
        adj_sm[256 + tid] = adjb[(size_t)(2 * ch + 1) * NNODE + tid];
        __syncthreads();
        uint32_t Aw[2][4];
#pragma unroll
        for (int t = 0; t < 4; t++) {
            Aw[0][t] = adj_sm[r0 + t * 8 + g4];
            Aw[1][t] = adj_sm[256 + r0 + t * 8 + g4];
        }
#pragma unroll
        for (int kb = 0; kb < 8; kb++) {
            int jA = kb * 8 + q4;
            float4 jA4 = je[jA];
            float4 jB4 = je[jA + 4];
            int half = kb >> 2;
            int sh = jA & 31;
            uint32_t fr[2][4];
#pragma unroll
            for (int t = 0; t < 4; t++) {
                uint32_t Aword = Aw[half][t];
                uint32_t mA = (uint32_t)(((int32_t)(Aword << (31 - sh))) >> 31);
                uint32_t mB = (uint32_t)(((int32_t)(Aword << (27 - sh))) >> 31);
                float tA = jA4.x + adreg[t];
                float tB = jB4.x + adreg[t];
                float pA = slctf(jA4.y * F1[t], jA4.z * F2[t], tA);
                float pB = slctf(jB4.y * F1[t], jB4.z * F2[t], tB);
                fr[t >> 1][t & 1] = __float_as_uint(pA) & mA;
                fr[t >> 1][2 + (t & 1)] = __float_as_uint(pB) & mB;
            }
            const float* b0p = v2 + jA * V2S + g4 * 12;
            const float* b1p = b0p + 4 * V2S;
            float4 B0a = *(const float4*)b0p;
            float4 B0b = *(const float4*)(b0p + 4);
            float  B0c = b0p[8];
            float4 B1a = *(const float4*)b1p;
            float4 B1b = *(const float4*)(b1p + 4);
            float  B1c = b1p[8];
#pragma unroll
            for (int mt = 0; mt < 2; mt++) {
                uint32_t f0 = fr[mt][0], f1 = fr[mt][1], f2 = fr[mt][2], f3 = fr[mt][3];
                mma_tf32(acc[mt][0], f0, f1, f2, f3, __float_as_uint(B0a.x), __float_as_uint(B1a.x));
                mma_tf32(acc[mt][1], f0, f1, f2, f3, __float_as_uint(B0a.y), __float_as_uint(B1a.y));
                mma_tf32(acc[mt][2], f0, f1, f2, f3, __float_as_uint(B0a.z), __float_as_uint(B1a.z));
                mma_tf32(acc[mt][3], f0, f1, f2, f3, __float_as_uint(B0a.w), __float_as_uint(B1a.w));
                mma_tf32(acc[mt][4], f0, f1, f2, f3, __float_as_uint(B0b.x), __float_as_uint(B1b.x));
                mma_tf32(acc[mt][5], f0, f1, f2, f3, __float_as_uint(B0b.y), __float_as_uint(B1b.y));
                mma_tf32(acc[mt][6], f0, f1, f2, f3, __float_as_uint(B0b.z), __float_as_uint(B1b.z));
                mma_tf32(acc[mt][7], f0, f1, f2, f3, __float_as_uint(B0b.w), __float_as_uint(B1b.w));
                mma_tf32(acc[mt][8], f0, f1, f2, f3, __float_as_uint(B0c), __float_as_uint(B1c));
            }
        }
    }
    const float* bp = gbias + hh * 64;
#pragma unroll
    for (int mt = 0; mt < 2; mt++) {
        float iz0 = 1.f / acc[mt][8][0];
        float iz1 = 1.f / acc[mt][8][2];
        int rowg = i0 + r0 + mt * 16 + g4;
        float* o0 = hout + ((size_t)(b * NNODE) + rowg) * DIM + hh * 64;
        float* o1 = o0 + 8 * DIM;
#pragma unroll
        for (int nt = 0; nt < 8; nt++) {
            int cc = nt * 8 + q4 * 2;
            float bx = bp[cc], by = bp[cc + 1];
            float2 u0, u1;
            u0.x = fmaxf(fmaf(acc[mt][nt][0], iz0, bx), 0.f);
            u0.y = fmaxf(fmaf(acc[mt][nt][1], iz0, by), 0.f);
            u1.x = fmaxf(fmaf(acc[mt][nt][2], iz1, bx), 0.f);
            u1.y = fmaxf(fmaf(acc[mt][nt][3], iz1, by), 0.f);
            *(float2*)(o0 + cc) = u0;
            *(float2*)(o1 + cc) = u1;
        }
    }
}

// ---------------- zero tail of output (mask = all false) ----------------
__global__ void zero_tail_kernel(float* out, long long start, long long total)
{
    long long i = start + (long long)blockIdx.x * blockDim.x + threadIdx.x;
    if (i < total) out[i] = 0.f;
}

// ---------------- launch ----------------
extern "C" void kernel_launch(void* const* d_in, const int* in_sizes, int n_in,
                              void* d_out, int out_size)
{
    const float* ego      = (const float*)d_in[0];
    const float* nbr      = (const float*)d_in[1];
    const float* node_w   = (const float*)d_in[2];
    const float* node_b   = (const float*)d_in[3];
    const float* node_g   = (const float*)d_in[4];
    const float* node_bb  = (const float*)d_in[5];
    const float* ego_w    = (const float*)d_in[6];
    const float* ego_b    = (const float*)d_in[7];
    const float* ego_g    = (const float*)d_in[8];
    const float* ego_bb   = (const float*)d_in[9];
    const float* gat_w    = (const float*)d_in[10];
    const float* gat_asrc = (const float*)d_in[11];
    const float* gat_adst = (const float*)d_in[12];
    const float* gat_b    = (const float*)d_in[13];
    const float* proj_w   = (const float*)d_in[14];
    const float* proj_b   = (const float*)d_in[15];
    float* out = (float*)d_out;

    float *h0, *h1, *wh;
    cudaGetSymbolAddress((void**)&h0, g_h0);
    cudaGetSymbolAddress((void**)&h1, g_h1);
    cudaGetSymbolAddress((void**)&wh, g_wh);

    embed_kernel<<<BATCH * NNODE / 8, 256>>>(ego, nbr, node_w, node_b, node_g, node_bb,
                                             ego_w, ego_b, ego_g, ego_bb);
    adj_kernel<<<dim3(NNODE / 32, 32, BATCH), 256>>>();

    long long hsz = (long long)BATCH * NNODE * DIM;
    if ((long long)out_size > hsz) {
        long long tail = (long long)out_size - hsz;
        int blocks = (int)((tail + 255) / 256);
        zero_tail_kernel<<<blocks, 256>>>(out, hsz, (long long)out_size);
    }

    dim3 ggrid(BATCH * NNODE / 128, 4);
    float* hbuf[2] = { h0, h1 };
    for (int l = 0; l < 2; l++) {
        tgemm256<false, true><<<ggrid, 256>>>(hbuf[l], gat_w + (long long)l * DIM * DIM,
                                              nullptr, wh,
                                              gat_asrc + l * HEADS * 64,
                                              gat_adst + l * HEADS * 64, l);
        gat_attn_mma<<<dim3(4, HEADS, BATCH), 256>>>(wh, gat_b + l * DIM, hbuf[1 - l], l);
    }
    tgemm256<true, false><<<ggrid, 256>>>(h0, proj_w, proj_b, out, nullptr, nullptr, 0);
}

// round 10
// speedup vs baseline: 1.2896x; 1.2896x over previous
#include <cuda_runtime.h>
#include <cstdint>

#define BATCH 16
#define NNODE 1024
#define DIM 256
#define HEADS 4
#define NBR 1023
#define TSTEPS 20

// ---------------- scratch (device globals; no allocation allowed) ----------------
__device__ float g_h0[BATCH * NNODE * DIM];
__device__ float g_h1[BATCH * NNODE * DIM];
__device__ float g_wh[BATCH * NNODE * DIM];
__device__ float g_pos[BATCH * NNODE * 2];
__device__ float g_as[BATCH * HEADS * NNODE];
__device__ float g_ad[BATCH * HEADS * NNODE];
__device__ uint32_t g_asmaxu[2 * BATCH * HEADS];  // [layer][bh], order-preserving enc
__device__ uint32_t g_adjT[BATCH * 32 * NNODE];   // [b][jword][i] bit lane = j%32

// ======================= helpers =======================
__device__ __forceinline__ uint32_t tf32r(float x) {
    uint32_t r;
    asm("cvt.rna.tf32.f32 %0, %1;" : "=r"(r) : "f"(x));
    return r;
}
__device__ __forceinline__ void mma_tf32(float* c, uint32_t a0, uint32_t a1,
                                         uint32_t a2, uint32_t a3,
                                         uint32_t b0, uint32_t b1) {
    asm volatile(
        "mma.sync.aligned.m16n8k8.row.col.f32.tf32.tf32.f32 "
        "{%0,%1,%2,%3}, {%4,%5,%6,%7}, {%8,%9}, {%0,%1,%2,%3};"
        : "+f"(c[0]), "+f"(c[1]), "+f"(c[2]), "+f"(c[3])
        : "r"(a0), "r"(a1), "r"(a2), "r"(a3), "r"(b0), "r"(b1));
}
__device__ __forceinline__ float slctf(float a, float b, float c) {
    float d;
    asm("slct.f32.f32 %0, %1, %2, %3;" : "=f"(d) : "f"(a), "f"(b), "f"(c));
    return d;
}
__device__ __forceinline__ uint32_t fenc(float f) {
    uint32_t b = __float_as_uint(f);
    return ((int)b < 0) ? ~b : (b | 0x80000000u);
}
__device__ __forceinline__ float fdec(uint32_t u) {
    return __uint_as_float((u & 0x80000000u) ? (u ^ 0x80000000u) : ~u);
}

// ---------------- embed: 8 nodes per block, weight col in regs ----------------
__global__ __launch_bounds__(256) void embed_kernel(
    const float* __restrict__ ego, const float* __restrict__ nbr,
    const float* __restrict__ node_w, const float* __restrict__ node_b,
    const float* __restrict__ node_g, const float* __restrict__ node_bb,
    const float* __restrict__ ego_w, const float* __restrict__ ego_b,
    const float* __restrict__ ego_g, const float* __restrict__ ego_bb)
{
    int t = threadIdx.x;
    int bn0 = blockIdx.x * 8;
    __shared__ float f[8][5];
    __shared__ float ws[8][8], wq[8][8];
    if (t < 40) {
        int nn = t / 5, k = t - nn * 5;
        int bn = bn0 + nn;
        int b = bn >> 10, n = bn & 1023;
        float v = (n == 0) ? ego[(b * TSTEPS + TSTEPS - 1) * 7 + k]
                           : nbr[((b * NBR + (n - 1)) * TSTEPS + TSTEPS - 1) * 11 + k];
        f[nn][k] = v;
        if (k < 2) g_pos[bn * 2 + k] = v;
    }
    __syncthreads();
    float wn[5];
#pragma unroll
    for (int k = 0; k < 5; k++) wn[k] = node_w[k * DIM + t];
    float nb = node_b[t];
    int lane = t & 31, w = t >> 5;
    float vv[8];
#pragma unroll
    for (int nn = 0; nn < 8; nn++) {
        int n = (bn0 + nn) & 1023;
        float v;
        if (n == 0) {
            v = ego_b[t];
#pragma unroll
            for (int k = 0; k < 5; k++) v = fmaf(f[nn][k], ego_w[k * DIM + t], v);
        } else {
            v = nb;
#pragma unroll
            for (int k = 0; k < 5; k++) v = fmaf(f[nn][k], wn[k], v);
        }
        v = fmaxf(v, 0.f);
        vv[nn] = v;
        float s = v, q = v * v;
#pragma unroll
        for (int o = 16; o; o >>= 1) {
            s += __shfl_down_sync(0xffffffffu, s, o);
            q += __shfl_down_sync(0xffffffffu, q, o);
        }
        if (lane == 0) { ws[nn][w] = s; wq[nn][w] = q; }
    }
    __syncthreads();
    float ng = node_g[t], nbb = node_bb[t];
#pragma unroll
    for (int nn = 0; nn < 8; nn++) {
        int bn = bn0 + nn;
        int n = bn & 1023;
        float sum = 0.f, sq = 0.f;
#pragma unroll
        for (int i = 0; i < 8; i++) { sum += ws[nn][i]; sq += wq[nn][i]; }
        float mean = sum * (1.f / 256.f);
        float var = fmaxf(sq * (1.f / 256.f) - mean * mean, 0.f);
        float inv = rsqrtf(var + 1e-5f);
        float gg = ng, bb2 = nbb;
        if (n == 0) { gg = ego_g[t]; bb2 = ego_bb[t]; }
        g_h0[(size_t)bn * DIM + t] = (vv[nn] - mean) * inv * gg + bb2;
    }
}

// ---------------- adjacency bitmask + asmax buffer init ----------------
__global__ __launch_bounds__(256) void adj_kernel()
{
    int b = blockIdx.z, jw = blockIdx.y;
    int lane = threadIdx.x & 31, w = threadIdx.x >> 5;
    if (blockIdx.x == 0 && jw == 0 && threadIdx.x < 8) {
        int l = threadIdx.x >> 2, h = threadIdx.x & 3;
        g_asmaxu[l * (BATCH * HEADS) + b * HEADS + h] = 0u;
    }
    int j = jw * 32 + lane;
    float2 pj = ((const float2*)g_pos)[b * NNODE + j];
    int i0 = blockIdx.x * 32 + w;
#pragma unroll
    for (int q = 0; q < 4; q++) {
        int i = i0 + q * 8;
        float2 pi = ((const float2*)g_pos)[b * NNODE + i];
        float dx = pj.x - pi.x, dy = pj.y - pi.y;
        bool a = (fmaf(dx, dx, dy * dy) < 2500.f) || (i == j);
        uint32_t word = __ballot_sync(0xffffffffu, a);
        if (lane == 0) g_adjT[(b * 32 + jw) * NNODE + i] = word;
    }
}

// ---------------- tf32 tensor-core GEMM (+fused a_src/a_dst + asmax) ----------
#define GA_STRIDE 36
#define GB_STRIDE 72
template <bool BIAS, bool SAD>
__global__ __launch_bounds__(256) void tgemm256(
    const float* __restrict__ A, const float* __restrict__ W,
    const float* __restrict__ bias, float* __restrict__ C,
    const float* __restrict__ asrc, const float* __restrict__ adst,
    int sadLayer)
{
    __shared__ float As[128 * GA_STRIDE];
    __shared__ float Bs[32 * GB_STRIDE];
    int tid = threadIdx.x, w = tid >> 5, lane = tid & 31;
    int g4 = lane >> 2, q4 = lane & 3;
    int m0 = blockIdx.x * 128, n0 = blockIdx.y * 64;
    int wm = w & 3, wn = w >> 2;
    int r0 = wm * 32, c0 = wn * 32;

    int af4 = tid & 7, arow = tid >> 3;
    int bf4 = tid & 15, brow = tid >> 4;
    const float* Ag = A + (size_t)(m0 + arow) * 256 + af4 * 4;
    const float* Wg = W + (size_t)brow * 256 + n0 + bf4 * 4;

    float acc[2][4][4];
#pragma unroll
    for (int mt = 0; mt < 2; mt++)
#pragma unroll
        for (int nt = 0; nt < 4; nt++)
#pragma unroll
            for (int k = 0; k < 4; k++) acc[mt][nt][k] = 0.f;

    float4 pa[4], pb[2];
#pragma unroll
    for (int q = 0; q < 4; q++) pa[q] = *(const float4*)(Ag + (size_t)q * 32 * 256);
#pragma unroll
    for (int q = 0; q < 2; q++) pb[q] = *(const float4*)(Wg + (size_t)q * 16 * 256);

    for (int kc = 0; kc < 8; kc++) {
        __syncthreads();
#pragma unroll
        for (int q = 0; q < 4; q++) {
            float* d = As + (arow + q * 32) * GA_STRIDE + af4 * 4;
            d[0] = __uint_as_float(tf32r(pa[q].x));
            d[1] = __uint_as_float(tf32r(pa[q].y));
            d[2] = __uint_as_float(tf32r(pa[q].z));
            d[3] = __uint_as_float(tf32r(pa[q].w));
        }
#pragma unroll
        for (int q = 0; q < 2; q++) {
            float* d = Bs + (brow + q * 16) * GB_STRIDE + bf4 * 4;
            d[0] = __uint_as_float(tf32r(pb[q].x));
            d[1] = __uint_as_float(tf32r(pb[q].y));
            d[2] = __uint_as_float(tf32r(pb[q].z));
            d[3] = __uint_as_float(tf32r(pb[q].w));
        }
        __syncthreads();
        if (kc < 7) {
            const float* Agn = Ag + (kc + 1) * 32;
            const float* Wgn = Wg + (size_t)(kc + 1) * 32 * 256;
#pragma unroll
            for (int q = 0; q < 4; q++) pa[q] = *(const float4*)(Agn + (size_t)q * 32 * 256);
#pragma unroll
            for (int q = 0; q < 2; q++) pb[q] = *(const float4*)(Wgn + (size_t)q * 16 * 256);
        }
#pragma unroll
        for (int kb = 0; kb < 4; kb++) {
            int k8 = kb * 8;
            const float* a0p = As + (r0 + g4) * GA_STRIDE + k8 + q4;
            uint32_t a00 = __float_as_uint(a0p[0]);
            uint32_t a01 = __float_as_uint(a0p[8 * GA_STRIDE]);
            uint32_t a02 = __float_as_uint(a0p[4]);
            uint32_t a03 = __float_as_uint(a0p[8 * GA_STRIDE + 4]);
            uint32_t a10 = __float_as_uint(a0p[16 * GA_STRIDE]);
            uint32_t a11 = __float_as_uint(a0p[24 * GA_STRIDE]);
            uint32_t a12 = __float_as_uint(a0p[16 * GA_STRIDE + 4]);
            uint32_t a13 = __float_as_uint(a0p[24 * GA_STRIDE + 4]);
            const float* bp = Bs + (k8 + q4) * GB_STRIDE + c0 + g4;
#pragma unroll
            for (int nt = 0; nt < 4; nt++) {
                uint32_t b0 = __float_as_uint(bp[nt * 8]);
                uint32_t b1 = __float_as_uint(bp[nt * 8 + 4 * GB_STRIDE]);
                mma_tf32(acc[0][nt], a00, a01, a02, a03, b0, b1);
                mma_tf32(acc[1][nt], a10, a11, a12, a13, b0, b1);
            }
        }
    }
    // ---- C store ----
#pragma unroll
    for (int mt = 0; mt < 2; mt++) {
        int row = m0 + r0 + mt * 16 + g4;
        float* c0p = C + (size_t)row * 256 + n0 + c0;
        float* c1p = c0p + 8 * 256;
#pragma unroll
        for (int nt = 0; nt < 4; nt++) {
            int cc = nt * 8 + q4 * 2;
            float bx = 0.f, by = 0.f;
            if (BIAS) { bx = bias[n0 + c0 + cc]; by = bias[n0 + c0 + cc + 1]; }
            float2 u0, u1;
            u0.x = acc[mt][nt][0] + bx; u0.y = acc[mt][nt][1] + by;
            u1.x = acc[mt][nt][2] + bx; u1.y = acc[mt][nt][3] + by;
            *(float2*)(c0p + cc) = u0;
            *(float2*)(c1p + cc) = u1;
        }
    }
    // ---- fused a_src / a_dst + asmax (block covers one full head's 64 cols) ----
    if (SAD) {
        float as_c[8], ad_c[8];
#pragma unroll
        for (int nt = 0; nt < 4; nt++) {
            int cg = n0 + c0 + nt * 8 + q4 * 2;
            as_c[nt * 2] = asrc[cg]; as_c[nt * 2 + 1] = asrc[cg + 1];
            ad_c[nt * 2] = adst[cg]; ad_c[nt * 2 + 1] = adst[cg + 1];
        }
        __syncthreads();                 // As no longer read; reuse as reduction buffer
        float* red = As;
#pragma unroll
        for (int mt = 0; mt < 2; mt++) {
            float sAs = 0.f, sAd = 0.f, sBs = 0.f, sBd = 0.f;
#pragma unroll
            for (int nt = 0; nt < 4; nt++) {
                sAs += acc[mt][nt][0] * as_c[nt * 2] + acc[mt][nt][1] * as_c[nt * 2 + 1];
                sBs += acc[mt][nt][2] * as_c[nt * 2] + acc[mt][nt][3] * as_c[nt * 2 + 1];
                sAd += acc[mt][nt][0] * ad_c[nt * 2] + acc[mt][nt][1] * ad_c[nt * 2 + 1];
                sBd += acc[mt][nt][2] * ad_c[nt * 2] + acc[mt][nt][3] * ad_c[nt * 2 + 1];
            }
#pragma unroll
            for (int o = 1; o < 4; o <<= 1) {
                sAs += __shfl_xor_sync(0xffffffffu, sAs, o);
                sAd += __shfl_xor_sync(0xffffffffu, sAd, o);
                sBs += __shfl_xor_sync(0xffffffffu, sBs, o);
                sBd += __shfl_xor_sync(0xffffffffu, sBd, o);
            }
            if (q4 == 0) {
                int rA = r0 + mt * 16 + g4, rB = rA + 8;
                *(float2*)&red[(rA * 2 + wn) * 2] = make_float2(sAs, sAd);
                *(float2*)&red[(rB * 2 + wn) * 2] = make_float2(sBs, sBd);
            }
        }
        __syncthreads();
        if (tid < 128) {
            float2 v0 = *(float2*)&red[(tid * 2 + 0) * 2];
            float2 v1 = *(float2*)&red[(tid * 2 + 1) * 2];
            int b = m0 >> 10, n = (m0 & 1023) + tid;
            int bh = b * HEADS + blockIdx.y;
            float asv = v0.x + v1.x;
            g_as[bh * NNODE + n] = asv;
            g_ad[bh * NNODE + n] = v0.y + v1.y;
            float m = asv;
#pragma unroll
            for (int o = 16; o; o >>= 1)
                m = fmaxf(m, __shfl_xor_sync(0xffffffffu, m, o));
            if (lane == 0)
                atomicMax(&g_asmaxu[sadLayer * (BATCH * HEADS) + bh], fenc(m));
        }
    }
}

// ---------------- GAT attention: 256 rows/block, register-P tf32 mma.sync ----------
// (R8 row-major V layout, V_STRIDE=72 conflict-free; slct P-phase; fused-asmax read)
#define V_STRIDE 72
__global__ __launch_bounds__(256, 2) void gat_attn_mma(
    const float* __restrict__ wh, const float* __restrict__ gbias,
    float* __restrict__ hout, int layer)
{
    __shared__ float v_sm[64 * V_STRIDE];
    __shared__ float4 je[64];            // (as_j, E1_j, E2_j, -)
    __shared__ uint32_t adj_sm[512];

    int tid = threadIdx.x, w = tid >> 5, lane = tid & 31;
    int g4 = lane >> 2, q4 = lane & 3;
    int it = blockIdx.x, hh = blockIdx.y, b = blockIdx.z;
    int i0 = it * 256, bh = b * HEADS + hh;
    int r0 = w * 32;

    float F1[4], F2[4], adreg[4];
    {
        float mx = fdec(g_asmaxu[layer * (BATCH * HEADS) + bh]);
#pragma unroll
        for (int t = 0; t < 4; t++) {
            float ad = g_ad[bh * NNODE + i0 + r0 + t * 8 + g4];
            adreg[t] = ad;
            float mm = mx + ad;
            float mr = fmaxf(mm, 0.2f * mm);
            F1[t] = __expf(ad - mr);
            F2[t] = __expf(0.2f * ad - mr);
        }
    }
    // B cols 64..71: col 64 = ones (Z), rest zeros
#pragma unroll
    for (int q = 0; q < 2; q++) {
        int idx = q * 256 + tid;
        int jr = idx >> 3, cc = 64 + (idx & 7);
        v_sm[jr * V_STRIDE + cc] = (cc == 64) ? 1.f : 0.f;
    }

    float acc[2][9][4];
#pragma unroll
    for (int mt = 0; mt < 2; mt++)
#pragma unroll
        for (int n = 0; n < 9; n++)
#pragma unroll
            for (int k = 0; k < 4; k++) acc[mt][n][k] = 0.f;

    const float* whb = wh + ((size_t)(b * NNODE)) * DIM + hh * 64;
    const uint32_t* adjb = g_adjT + (size_t)b * 32 * NNODE + i0;

    for (int ch = 0; ch < 16; ch++) {
        int j0 = ch * 64;
        __syncthreads();
        // V chunk [64 x 64] -> v_sm (tf32-rounded), 4 float4 per thread
#pragma unroll
        for (int q = 0; q < 4; q++) {
            int idx = q * 256 + tid;
            int jr = idx >> 4, cc = (idx & 15) * 4;
            float4 v = *(const float4*)(whb + (size_t)(j0 + jr) * DIM + cc);
            float* dst = v_sm + jr * V_STRIDE + cc;
            dst[0] = __uint_as_float(tf32r(v.x));
            dst[1] = __uint_as_float(tf32r(v.y));
            dst[2] = __uint_as_float(tf32r(v.z));
            dst[3] = __uint_as_float(tf32r(v.w));
        }
        if (tid < 64) {
            float a = g_as[bh * NNODE + j0 + tid];
            je[tid] = make_float4(a, __expf(a), __expf(0.2f * a), 0.f);
        }
        adj_sm[tid] = adjb[(size_t)(2 * ch) * NNODE + tid];
        adj_sm[256 + tid] = adjb[(size_t)(2 * ch + 1) * NNODE + tid];
        __syncthreads();
        uint32_t Aw[2][4];
#pragma unroll
        for (int t = 0; t < 4; t++) {
            Aw[0][t] = adj_sm[r0 + t * 8 + g4];
            Aw[1][t] = adj_sm[256 + r0 + t * 8 + g4];
        }
#pragma unroll
        for (int kb = 0; kb < 8; kb++) {
            int jA = kb * 8 + q4;
            float4 jA4 = je[jA];
            float4 jB4 = je[jA + 4];
            int half = kb >> 2;
            int sh = jA & 31;
            uint32_t fr[2][4];
#pragma unroll
            for (int t = 0; t < 4; t++) {
                uint32_t Aword = Aw[half][t];
                uint32_t mA = (uint32_t)(((int32_t)(Aword << (31 - sh))) >> 31);
                uint32_t mB = (uint32_t)(((int32_t)(Aword << (27 - sh))) >> 31);
                float tA = jA4.x + adreg[t];
                float tB = jB4.x + adreg[t];
                float pA = slctf(jA4.y * F1[t], jA4.z * F2[t], tA);
                float pB = slctf(jB4.y * F1[t], jB4.z * F2[t], tB);
                fr[t >> 1][t & 1] = __float_as_uint(pA) & mA;
                fr[t >> 1][2 + (t & 1)] = __float_as_uint(pB) & mB;
            }
            const float* bp = v_sm + (kb * 8 + q4) * V_STRIDE + g4;
#pragma unroll
            for (int nt = 0; nt < 9; nt++) {
                uint32_t b0 = __float_as_uint(bp[nt * 8]);
                uint32_t b1 = __float_as_uint(bp[nt * 8 + 4 * V_STRIDE]);
                mma_tf32(acc[0][nt], fr[0][0], fr[0][1], fr[0][2], fr[0][3], b0, b1);
                mma_tf32(acc[1][nt], fr[1][0], fr[1][1], fr[1][2], fr[1][3], b0, b1);
            }
        }
    }
    const float* bp = gbias + hh * 64;
#pragma unroll
    for (int mt = 0; mt < 2; mt++) {
        float z0 = __shfl_sync(0xffffffffu, acc[mt][8][0], lane & 28);
        float z1 = __shfl_sync(0xffffffffu, acc[mt][8][2], lane & 28);
        float iz0 = 1.f / z0;
        float iz1 = 1.f / z1;
        int rowg = i0 + r0 + mt * 16 + g4;
        float* o0 = hout + ((size_t)(b * NNODE) + rowg) * DIM + hh * 64;
        float* o1 = o0 + 8 * DIM;
#pragma unroll
        for (int nt = 0; nt < 8; nt++) {
            int cc = nt * 8 + q4 * 2;
            float bx = bp[cc], by = bp[cc + 1];
            float2 u0, u1;
            u0.x = fmaxf(fmaf(acc[mt][nt][0], iz0, bx), 0.f);
            u0.y = fmaxf(fmaf(acc[mt][nt][1], iz0, by), 0.f);
            u1.x = fmaxf(fmaf(acc[mt][nt][2], iz1, bx), 0.f);
            u1.y = fmaxf(fmaf(acc[mt][nt][3], iz1, by), 0.f);
            *(float2*)(o0 + cc) = u0;
            *(float2*)(o1 + cc) = u1;
        }
    }
}

// ---------------- zero tail of output (mask = all false) ----------------
__global__ void zero_tail_kernel(float* out, long long start, long long total)
{
    long long i = start + (long long)blockIdx.x * blockDim.x + threadIdx.x;
    if (i < total) out[i] = 0.f;
}

// ---------------- launch ----------------
extern "C" void kernel_launch(void* const* d_in, const int* in_sizes, int n_in,
                              void* d_out, int out_size)
{
    const float* ego      = (const float*)d_in[0];
    const float* nbr      = (const float*)d_in[1];
    const float* node_w   = (const float*)d_in[2];
    const float* node_b   = (const float*)d_in[3];
    const float* node_g   = (const float*)d_in[4];
    const float* node_bb  = (const float*)d_in[5];
    const float* ego_w    = (const float*)d_in[6];
    const float* ego_b    = (const float*)d_in[7];
    const float* ego_g    = (const float*)d_in[8];
    const float* ego_bb   = (const float*)d_in[9];
    const float* gat_w    = (const float*)d_in[10];
    const float* gat_asrc = (const float*)d_in[11];
    const float* gat_adst = (const float*)d_in[12];
    const float* gat_b    = (const float*)d_in[13];
    const float* proj_w   = (const float*)d_in[14];
    const float* proj_b   = (const float*)d_in[15];
    float* out = (float*)d_out;

    float *h0, *h1, *wh;
    cudaGetSymbolAddress((void**)&h0, g_h0);
    cudaGetSymbolAddress((void**)&h1, g_h1);
    cudaGetSymbolAddress((void**)&wh, g_wh);

    embed_kernel<<<BATCH * NNODE / 8, 256>>>(ego, nbr, node_w, node_b, node_g, node_bb,
                                             ego_w, ego_b, ego_g, ego_bb);
    adj_kernel<<<dim3(NNODE / 32, 32, BATCH), 256>>>();

    long long hsz = (long long)BATCH * NNODE * DIM;
    if ((long long)out_size > hsz) {
        long long tail = (long long)out_size - hsz;
        int blocks = (int)((tail + 255) / 256);
        zero_tail_kernel<<<blocks, 256>>>(out, hsz, (long long)out_size);
    }

    dim3 ggrid(BATCH * NNODE / 128, 4);
    float* hbuf[2] = { h0, h1 };
    for (int l = 0; l < 2; l++) {
        tgemm256<false, true><<<ggrid, 256>>>(hbuf[l], gat_w + (long long)l * DIM * DIM,
                                              nullptr, wh,
                                              gat_asrc + l * HEADS * 64,
                                              gat_adst + l * HEADS * 64, l);
        gat_attn_mma<<<dim3(4, HEADS, BATCH), 256>>>(wh, gat_b + l * DIM, hbuf[1 - l], l);
    }
    tgemm256<true, false><<<ggrid, 256>>>(h0, proj_w, proj_b, out, nullptr, nullptr, 0);
}

// round 11
// speedup vs baseline: 1.5976x; 1.2388x over previous
#include <cuda_runtime.h>
#include <cstdint>

#define BATCH 16
#define NNODE 1024
#define DIM 256
#define HEADS 4
#define NBR 1023
#define TSTEPS 20

// ---------------- scratch (device globals; no allocation allowed) ----------------
__device__ float g_h0[BATCH * NNODE * DIM];
__device__ float g_h1[BATCH * NNODE * DIM];
__device__ float g_wh[BATCH * NNODE * DIM];
__device__ float g_pos[BATCH * NNODE * 2];
__device__ float g_as[BATCH * HEADS * NNODE];
__device__ float g_ad[BATCH * HEADS * NNODE];
__device__ uint32_t g_asmaxu[2 * BATCH * HEADS];  // [layer][bh], order-preserving enc
__device__ uint32_t g_adjT[BATCH * 32 * NNODE];   // [b][jword][i] bit lane = j%32

// ======================= helpers =======================
__device__ __forceinline__ uint32_t tf32r(float x) {
    uint32_t r;
    asm("cvt.rna.tf32.f32 %0, %1;" : "=r"(r) : "f"(x));
    return r;
}
__device__ __forceinline__ void mma_tf32(float* c, uint32_t a0, uint32_t a1,
                                         uint32_t a2, uint32_t a3,
                                         uint32_t b0, uint32_t b1) {
    asm volatile(
        "mma.sync.aligned.m16n8k8.row.col.f32.tf32.tf32.f32 "
        "{%0,%1,%2,%3}, {%4,%5,%6,%7}, {%8,%9}, {%0,%1,%2,%3};"
        : "+f"(c[0]), "+f"(c[1]), "+f"(c[2]), "+f"(c[3])
        : "r"(a0), "r"(a1), "r"(a2), "r"(a3), "r"(b0), "r"(b1));
}
__device__ __forceinline__ void mma_f16(float* c, uint32_t a0, uint32_t a1,
                                        uint32_t a2, uint32_t a3,
                                        uint32_t b0, uint32_t b1) {
    asm volatile(
        "mma.sync.aligned.m16n8k16.row.col.f32.f16.f16.f32 "
        "{%0,%1,%2,%3}, {%4,%5,%6,%7}, {%8,%9}, {%0,%1,%2,%3};"
        : "+f"(c[0]), "+f"(c[1]), "+f"(c[2]), "+f"(c[3])
        : "r"(a0), "r"(a1), "r"(a2), "r"(a3), "r"(b0), "r"(b1));
}
__device__ __forceinline__ float slctf(float a, float b, float c) {
    float d;
    asm("slct.f32.f32 %0, %1, %2, %3;" : "=f"(d) : "f"(a), "f"(b), "f"(c));
    return d;
}
__device__ __forceinline__ uint32_t pack2(float lo, float hi) {
    uint32_t d;
    asm("cvt.rn.f16x2.f32 %0, %1, %2;" : "=r"(d) : "f"(hi), "f"(lo));
    return d;
}
__device__ __forceinline__ uint32_t fenc(float f) {
    uint32_t b = __float_as_uint(f);
    return ((int)b < 0) ? ~b : (b | 0x80000000u);
}
__device__ __forceinline__ float fdec(uint32_t u) {
    return __uint_as_float((u & 0x80000000u) ? (u ^ 0x80000000u) : ~u);
}

// ---------------- embed: 8 nodes per block, weight col in regs ----------------
__global__ __launch_bounds__(256) void embed_kernel(
    const float* __restrict__ ego, const float* __restrict__ nbr,
    const float* __restrict__ node_w, const float* __restrict__ node_b,
    const float* __restrict__ node_g, const float* __restrict__ node_bb,
    const float* __restrict__ ego_w, const float* __restrict__ ego_b,
    const float* __restrict__ ego_g, const float* __restrict__ ego_bb)
{
    int t = threadIdx.x;
    int bn0 = blockIdx.x * 8;
    __shared__ float f[8][5];
    __shared__ float ws[8][8], wq[8][8];
    if (t < 40) {
        int nn = t / 5, k = t - nn * 5;
        int bn = bn0 + nn;
        int b = bn >> 10, n = bn & 1023;
        float v = (n == 0) ? ego[(b * TSTEPS + TSTEPS - 1) * 7 + k]
                           : nbr[((b * NBR + (n - 1)) * TSTEPS + TSTEPS - 1) * 11 + k];
        f[nn][k] = v;
        if (k < 2) g_pos[bn * 2 + k] = v;
    }
    __syncthreads();
    float wn[5];
#pragma unroll
    for (int k = 0; k < 5; k++) wn[k] = node_w[k * DIM + t];
    float nb = node_b[t];
    int lane = t & 31, w = t >> 5;
    float vv[8];
#pragma unroll
    for (int nn = 0; nn < 8; nn++) {
        int n = (bn0 + nn) & 1023;
        float v;
        if (n == 0) {
            v = ego_b[t];
#pragma unroll
            for (int k = 0; k < 5; k++) v = fmaf(f[nn][k], ego_w[k * DIM + t], v);
        } else {
            v = nb;
#pragma unroll
            for (int k = 0; k < 5; k++) v = fmaf(f[nn][k], wn[k], v);
        }
        v = fmaxf(v, 0.f);
        vv[nn] = v;
        float s = v, q = v * v;
#pragma unroll
        for (int o = 16; o; o >>= 1) {
            s += __shfl_down_sync(0xffffffffu, s, o);
            q += __shfl_down_sync(0xffffffffu, q, o);
        }
        if (lane == 0) { ws[nn][w] = s; wq[nn][w] = q; }
    }
    __syncthreads();
    float ng = node_g[t], nbb = node_bb[t];
#pragma unroll
    for (int nn = 0; nn < 8; nn++) {
        int bn = bn0 + nn;
        int n = bn & 1023;
        float sum = 0.f, sq = 0.f;
#pragma unroll
        for (int i = 0; i < 8; i++) { sum += ws[nn][i]; sq += wq[nn][i]; }
        float mean = sum * (1.f / 256.f);
        float var = fmaxf(sq * (1.f / 256.f) - mean * mean, 0.f);
        float inv = rsqrtf(var + 1e-5f);
        float gg = ng, bb2 = nbb;
        if (n == 0) { gg = ego_g[t]; bb2 = ego_bb[t]; }
        g_h0[(size_t)bn * DIM + t] = (vv[nn] - mean) * inv * gg + bb2;
    }
}

// ---------------- adjacency bitmask + asmax buffer init ----------------
__global__ __launch_bounds__(256) void adj_kernel()
{
    int b = blockIdx.z, jw = blockIdx.y;
    int lane = threadIdx.x & 31, w = threadIdx.x >> 5;
    if (blockIdx.x == 0 && jw == 0 && threadIdx.x < 8) {
        int l = threadIdx.x >> 2, h = threadIdx.x & 3;
        g_asmaxu[l * (BATCH * HEADS) + b * HEADS + h] = 0u;
    }
    int j = jw * 32 + lane;
    float2 pj = ((const float2*)g_pos)[b * NNODE + j];
    int i0 = blockIdx.x * 32 + w;
#pragma unroll
    for (int q = 0; q < 4; q++) {
        int i = i0 + q * 8;
        float2 pi = ((const float2*)g_pos)[b * NNODE + i];
        float dx = pj.x - pi.x, dy = pj.y - pi.y;
        bool a = (fmaf(dx, dx, dy * dy) < 2500.f) || (i == j);
        uint32_t word = __ballot_sync(0xffffffffu, a);
        if (lane == 0) g_adjT[(b * 32 + jw) * NNODE + i] = word;
    }
}

// ---------------- tf32 tensor-core GEMM (+fused a_src/a_dst + asmax) ----------
#define GA_STRIDE 36
#define GB_STRIDE 72
template <bool BIAS, bool SAD>
__global__ __launch_bounds__(256) void tgemm256(
    const float* __restrict__ A, const float* __restrict__ W,
    const float* __restrict__ bias, float* __restrict__ C,
    const float* __restrict__ asrc, const float* __restrict__ adst,
    int sadLayer)
{
    __shared__ float As[128 * GA_STRIDE];
    __shared__ float Bs[32 * GB_STRIDE];
    int tid = threadIdx.x, w = tid >> 5, lane = tid & 31;
    int g4 = lane >> 2, q4 = lane & 3;
    int m0 = blockIdx.x * 128, n0 = blockIdx.y * 64;
    int wm = w & 3, wn = w >> 2;
    int r0 = wm * 32, c0 = wn * 32;

    int af4 = tid & 7, arow = tid >> 3;
    int bf4 = tid & 15, brow = tid >> 4;
    const float* Ag = A + (size_t)(m0 + arow) * 256 + af4 * 4;
    const float* Wg = W + (size_t)brow * 256 + n0 + bf4 * 4;

    float acc[2][4][4];
#pragma unroll
    for (int mt = 0; mt < 2; mt++)
#pragma unroll
        for (int nt = 0; nt < 4; nt++)
#pragma unroll
            for (int k = 0; k < 4; k++) acc[mt][nt][k] = 0.f;

    float4 pa[4], pb[2];
#pragma unroll
    for (int q = 0; q < 4; q++) pa[q] = *(const float4*)(Ag + (size_t)q * 32 * 256);
#pragma unroll
    for (int q = 0; q < 2; q++) pb[q] = *(const float4*)(Wg + (size_t)q * 16 * 256);

    for (int kc = 0; kc < 8; kc++) {
        __syncthreads();
#pragma unroll
        for (int q = 0; q < 4; q++) {
            float* d = As + (arow + q * 32) * GA_STRIDE + af4 * 4;
            d[0] = __uint_as_float(tf32r(pa[q].x));
            d[1] = __uint_as_float(tf32r(pa[q].y));
            d[2] = __uint_as_float(tf32r(pa[q].z));
            d[3] = __uint_as_float(tf32r(pa[q].w));
        }
#pragma unroll
        for (int q = 0; q < 2; q++) {
            float* d = Bs + (brow + q * 16) * GB_STRIDE + bf4 * 4;
            d[0] = __uint_as_float(tf32r(pb[q].x));
            d[1] = __uint_as_float(tf32r(pb[q].y));
            d[2] = __uint_as_float(tf32r(pb[q].z));
            d[3] = __uint_as_float(tf32r(pb[q].w));
        }
        __syncthreads();
        if (kc < 7) {
            const float* Agn = Ag + (kc + 1) * 32;
            const float* Wgn = Wg + (size_t)(kc + 1) * 32 * 256;
#pragma unroll
            for (int q = 0; q < 4; q++) pa[q] = *(const float4*)(Agn + (size_t)q * 32 * 256);
#pragma unroll
            for (int q = 0; q < 2; q++) pb[q] = *(const float4*)(Wgn + (size_t)q * 16 * 256);
        }
#pragma unroll
        for (int kb = 0; kb < 4; kb++) {
            int k8 = kb * 8;
            const float* a0p = As + (r0 + g4) * GA_STRIDE + k8 + q4;
            uint32_t a00 = __float_as_uint(a0p[0]);
            uint32_t a01 = __float_as_uint(a0p[8 * GA_STRIDE]);
            uint32_t a02 = __float_as_uint(a0p[4]);
            uint32_t a03 = __float_as_uint(a0p[8 * GA_STRIDE + 4]);
            uint32_t a10 = __float_as_uint(a0p[16 * GA_STRIDE]);
            uint32_t a11 = __float_as_uint(a0p[24 * GA_STRIDE]);
            uint32_t a12 = __float_as_uint(a0p[16 * GA_STRIDE + 4]);
            uint32_t a13 = __float_as_uint(a0p[24 * GA_STRIDE + 4]);
            const float* bp = Bs + (k8 + q4) * GB_STRIDE + c0 + g4;
#pragma unroll
            for (int nt = 0; nt < 4; nt++) {
                uint32_t b0 = __float_as_uint(bp[nt * 8]);
                uint32_t b1 = __float_as_uint(bp[nt * 8 + 4 * GB_STRIDE]);
                mma_tf32(acc[0][nt], a00, a01, a02, a03, b0, b1);
                mma_tf32(acc[1][nt], a10, a11, a12, a13, b0, b1);
            }
        }
    }
    // ---- C store ----
#pragma unroll
    for (int mt = 0; mt < 2; mt++) {
        int row = m0 + r0 + mt * 16 + g4;
        float* c0p = C + (size_t)row * 256 + n0 + c0;
        float* c1p = c0p + 8 * 256;
#pragma unroll
        for (int nt = 0; nt < 4; nt++) {
            int cc = nt * 8 + q4 * 2;
            float bx = 0.f, by = 0.f;
            if (BIAS) { bx = bias[n0 + c0 + cc]; by = bias[n0 + c0 + cc + 1]; }
            float2 u0, u1;
            u0.x = acc[mt][nt][0] + bx; u0.y = acc[mt][nt][1] + by;
            u1.x = acc[mt][nt][2] + bx; u1.y = acc[mt][nt][3] + by;
            *(float2*)(c0p + cc) = u0;
            *(float2*)(c1p + cc) = u1;
        }
    }
    // ---- fused a_src / a_dst + asmax ----
    if (SAD) {
        float as_c[8], ad_c[8];
#pragma unroll
        for (int nt = 0; nt < 4; nt++) {
            int cg = n0 + c0 + nt * 8 + q4 * 2;
            as_c[nt * 2] = asrc[cg]; as_c[nt * 2 + 1] = asrc[cg + 1];
            ad_c[nt * 2] = adst[cg]; ad_c[nt * 2 + 1] = adst[cg + 1];
        }
        __syncthreads();
        float* red = As;
#pragma unroll
        for (int mt = 0; mt < 2; mt++) {
            float sAs = 0.f, sAd = 0.f, sBs = 0.f, sBd = 0.f;
#pragma unroll
            for (int nt = 0; nt < 4; nt++) {
                sAs += acc[mt][nt][0] * as_c[nt * 2] + acc[mt][nt][1] * as_c[nt * 2 + 1];
                sBs += acc[mt][nt][2] * as_c[nt * 2] + acc[mt][nt][3] * as_c[nt * 2 + 1];
                sAd += acc[mt][nt][0] * ad_c[nt * 2] + acc[mt][nt][1] * ad_c[nt * 2 + 1];
                sBd += acc[mt][nt][2] * ad_c[nt * 2] + acc[mt][nt][3] * ad_c[nt * 2 + 1];
            }
#pragma unroll
            for (int o = 1; o < 4; o <<= 1) {
                sAs += __shfl_xor_sync(0xffffffffu, sAs, o);
                sAd += __shfl_xor_sync(0xffffffffu, sAd, o);
                sBs += __shfl_xor_sync(0xffffffffu, sBs, o);
                sBd += __shfl_xor_sync(0xffffffffu, sBd, o);
            }
            if (q4 == 0) {
                int rA = r0 + mt * 16 + g4, rB = rA + 8;
                *(float2*)&red[(rA * 2 + wn) * 2] = make_float2(sAs, sAd);
                *(float2*)&red[(rB * 2 + wn) * 2] = make_float2(sBs, sBd);
            }
        }
        __syncthreads();
        if (tid < 128) {
            float2 v0 = *(float2*)&red[(tid * 2 + 0) * 2];
            float2 v1 = *(float2*)&red[(tid * 2 + 1) * 2];
            int b = m0 >> 10, n = (m0 & 1023) + tid;
            int bh = b * HEADS + blockIdx.y;
            float asv = v0.x + v1.x;
            g_as[bh * NNODE + n] = asv;
            g_ad[bh * NNODE + n] = v0.y + v1.y;
            float m = asv;
#pragma unroll
            for (int o = 16; o; o >>= 1)
                m = fmaxf(m, __shfl_xor_sync(0xffffffffu, m, o));
            if (lane == 0)
                atomicMax(&g_asmaxu[sadLayer * (BATCH * HEADS) + bh], fenc(m));
        }
    }
}

// ---------------- GAT attention: fp16 m16n8k16 MMA, register-P, adj fast path ----
// v_p[jp][c] = half2( V[2jp][c], V[2jp+1][c] ); jp in [0,32), c in [0,72).
// Slots c 0..63 = V channels, c 64 = ones (Z), 65..71 zero.
#define VP_STRIDE 72
__global__ __launch_bounds__(256, 2) void gat_attn_mma(
    const float* __restrict__ wh, const float* __restrict__ gbias,
    float* __restrict__ hout, int layer)
{
    __shared__ uint32_t v_p[32 * VP_STRIDE];
    __shared__ float4 je[64];            // (as_j, E1_j, E2_j, -)
    __shared__ uint32_t adj_sm[512];

    int tid = threadIdx.x, w = tid >> 5, lane = tid & 31;
    int g4 = lane >> 2, q4 = lane & 3;
    int it = blockIdx.x, hh = blockIdx.y, b = blockIdx.z;
    int i0 = it * 256, bh = b * HEADS + hh;
    int r0 = w * 32;

    float F1[4], F2[4], adreg[4];
    {
        float mx = fdec(g_asmaxu[layer * (BATCH * HEADS) + bh]);
#pragma unroll
        for (int t = 0; t < 4; t++) {
            float ad = g_ad[bh * NNODE + i0 + r0 + t * 8 + g4];
            adreg[t] = ad;
            float mm = mx + ad;
            float mr = fmaxf(mm, 0.2f * mm);
            F1[t] = __expf(ad - mr);
            F2[t] = __expf(0.2f * ad - mr);
        }
    }
    // slots 64..71: 64 = half2(1,1), rest zero (written once; fill touches only 0..63)
    {
        int jp = tid >> 3, cc = 64 + (tid & 7);
        v_p[jp * VP_STRIDE + cc] = (cc == 64) ? 0x3C003C00u : 0u;
    }

    float acc[2][9][4];
#pragma unroll
    for (int mt = 0; mt < 2; mt++)
#pragma unroll
        for (int n = 0; n < 9; n++)
#pragma unroll
            for (int k = 0; k < 4; k++) acc[mt][n][k] = 0.f;

    const float* whb = wh + ((size_t)(b * NNODE)) * DIM + hh * 64;
    const uint32_t* adjb = g_adjT + (size_t)b * 32 * NNODE + i0;

    for (int ch = 0; ch < 16; ch++) {
        int j0c = ch * 64;
        __syncthreads();
        // fill v_p: thread -> (jp = tid>>3, c = (tid&7)*8), rows 2jp, 2jp+1
        {
            int jp = tid >> 3, cb = (tid & 7) * 8;
            const float* rA = whb + (size_t)(j0c + 2 * jp) * DIM + cb;
            const float* rB = rA + DIM;
            float4 a0 = *(const float4*)rA, a1 = *(const float4*)(rA + 4);
            float4 b0 = *(const float4*)rB, b1 = *(const float4*)(rB + 4);
            uint4 o0, o1;
            o0.x = pack2(a0.x, b0.x); o0.y = pack2(a0.y, b0.y);
            o0.z = pack2(a0.z, b0.z); o0.w = pack2(a0.w, b0.w);
            o1.x = pack2(a1.x, b1.x); o1.y = pack2(a1.y, b1.y);
            o1.z = pack2(a1.z, b1.z); o1.w = pack2(a1.w, b1.w);
            *(uint4*)&v_p[jp * VP_STRIDE + cb] = o0;
            *(uint4*)&v_p[jp * VP_STRIDE + cb + 4] = o1;
        }
        if (tid < 64) {
            float a = g_as[bh * NNODE + j0c + tid];
            je[tid] = make_float4(a, __expf(a), __expf(0.2f * a), 0.f);
        }
        adj_sm[tid] = adjb[(size_t)(2 * ch) * NNODE + tid];
        adj_sm[256 + tid] = adjb[(size_t)(2 * ch + 1) * NNODE + tid];
        __syncthreads();
        uint32_t Aw[2][4];
#pragma unroll
        for (int t = 0; t < 4; t++) {
            Aw[0][t] = adj_sm[r0 + t * 8 + g4];
            Aw[1][t] = adj_sm[256 + r0 + t * 8 + g4];
        }
        uint32_t andall = Aw[0][0] & Aw[0][1] & Aw[0][2] & Aw[0][3]
                        & Aw[1][0] & Aw[1][1] & Aw[1][2] & Aw[1][3];
        bool allones = __all_sync(0xffffffffu, andall == 0xffffffffu);

#pragma unroll
        for (int kb = 0; kb < 4; kb++) {
            int jlo = kb * 16 + 2 * q4;          // chunk-local j of a0 pair
            float4 jeA = je[jlo];
            float4 jeB = je[jlo + 1];
            float4 jeC = je[jlo + 8];
            float4 jeD = je[jlo + 9];
            uint32_t afr[2][4];
            if (allones) {
#pragma unroll
                for (int t = 0; t < 4; t++) {
                    float pa = slctf(jeA.y * F1[t], jeA.z * F2[t], jeA.x + adreg[t]);
                    float pb = slctf(jeB.y * F1[t], jeB.z * F2[t], jeB.x + adreg[t]);
                    float pc = slctf(jeC.y * F1[t], jeC.z * F2[t], jeC.x + adreg[t]);
                    float pd = slctf(jeD.y * F1[t], jeD.z * F2[t], jeD.x + adreg[t]);
                    afr[t >> 1][t & 1] = pack2(pa, pb);
                    afr[t >> 1][2 + (t & 1)] = pack2(pc, pd);
                }
            } else {
                int half = kb >> 1;
                int s = jlo & 31;                // bit of jlo; jlo+1 = s+1; hi pair at s+8
#pragma unroll
                for (int t = 0; t < 4; t++) {
                    uint32_t wv = Aw[half][t];
                    uint32_t b2lo = (wv >> s) & 3u;
                    uint32_t b2hi = (wv >> (s + 8)) & 3u;
                    uint32_t mlo = ((b2lo & 1u) ? 0x0000FFFFu : 0u) |
                                   ((b2lo & 2u) ? 0xFFFF0000u : 0u);
                    uint32_t mhi = ((b2hi & 1u) ? 0x0000FFFFu : 0u) |
                                   ((b2hi & 2u) ? 0xFFFF0000u : 0u);
                    float pa = slctf(jeA.y * F1[t], jeA.z * F2[t], jeA.x + adreg[t]);
                    float pb = slctf(jeB.y * F1[t], jeB.z * F2[t], jeB.x + adreg[t]);
                    float pc = slctf(jeC.y * F1[t], jeC.z * F2[t], jeC.x + adreg[t]);
                    float pd = slctf(jeD.y * F1[t], jeD.z * F2[t], jeD.x + adreg[t]);
                    afr[t >> 1][t & 1] = pack2(pa, pb) & mlo;
                    afr[t >> 1][2 + (t & 1)] = pack2(pc, pd) & mhi;
                }
            }
            const uint32_t* bp = v_p + (kb * 8 + q4) * VP_STRIDE + g4;
#pragma unroll
            for (int nt = 0; nt < 9; nt++) {
                uint32_t b0 = bp[nt * 8];
                uint32_t b1 = bp[nt * 8 + 4 * VP_STRIDE];
                mma_f16(acc[0][nt], afr[0][0], afr[0][1], afr[0][2], afr[0][3], b0, b1);
                mma_f16(acc[1][nt], afr[1][0], afr[1][1], afr[1][2], afr[1][3], b0, b1);
            }
        }
    }
    const float* bp = gbias + hh * 64;
#pragma unroll
    for (int mt = 0; mt < 2; mt++) {
        float z0 = __shfl_sync(0xffffffffu, acc[mt][8][0], lane & 28);
        float z1 = __shfl_sync(0xffffffffu, acc[mt][8][2], lane & 28);
        float iz0 = 1.f / z0;
        float iz1 = 1.f / z1;
        int rowg = i0 + r0 + mt * 16 + g4;
        float* o0 = hout + ((size_t)(b * NNODE) + rowg) * DIM + hh * 64;
        float* o1 = o0 + 8 * DIM;
#pragma unroll
        for (int nt = 0; nt < 8; nt++) {
            int cc = nt * 8 + q4 * 2;
            float bx = bp[cc], by = bp[cc + 1];
            float2 u0, u1;
            u0.x = fmaxf(fmaf(acc[mt][nt][0], iz0, bx), 0.f);
            u0.y = fmaxf(fmaf(acc[mt][nt][1], iz0, by), 0.f);
            u1.x = fmaxf(fmaf(acc[mt][nt][2], iz1, bx), 0.f);
            u1.y = fmaxf(fmaf(acc[mt][nt][3], iz1, by), 0.f);
            *(float2*)(o0 + cc) = u0;
            *(float2*)(o1 + cc) = u1;
        }
    }
}

// ---------------- zero tail of output (mask = all false) ----------------
__global__ void zero_tail_kernel(float* out, long long start, long long total)
{
    long long i = start + (long long)blockIdx.x * blockDim.x + threadIdx.x;
    if (i < total) out[i] = 0.f;
}

// ---------------- launch ----------------
extern "C" void kernel_launch(void* const* d_in, const int* in_sizes, int n_in,
                              void* d_out, int out_size)
{
    const float* ego      = (const float*)d_in[0];
    const float* nbr      = (const float*)d_in[1];
    const float* node_w   = (const float*)d_in[2];
    const float* node_b   = (const float*)d_in[3];
    const float* node_g   = (const float*)d_in[4];
    const float* node_bb  = (const float*)d_in[5];
    const float* ego_w    = (const float*)d_in[6];
    const float* ego_b    = (const float*)d_in[7];
    const float* ego_g    = (const float*)d_in[8];
    const float* ego_bb   = (const float*)d_in[9];
    const float* gat_w    = (const float*)d_in[10];
    const float* gat_asrc = (const float*)d_in[11];
    const float* gat_adst = (const float*)d_in[12];
    const float* gat_b    = (const float*)d_in[13];
    const float* proj_w   = (const float*)d_in[14];
    const float* proj_b   = (const float*)d_in[15];
    float* out = (float*)d_out;

    float *h0, *h1, *wh;
    cudaGetSymbolAddress((void**)&h0, g_h0);
    cudaGetSymbolAddress((void**)&h1, g_h1);
    cudaGetSymbolAddress((void**)&wh, g_wh);

    embed_kernel<<<BATCH * NNODE / 8, 256>>>(ego, nbr, node_w, node_b, node_g, node_bb,
                                             ego_w, ego_b, ego_g, ego_bb);
    adj_kernel<<<dim3(NNODE / 32, 32, BATCH), 256>>>();

    long long hsz = (long long)BATCH * NNODE * DIM;
    if ((long long)out_size > hsz) {
        long long tail = (long long)out_size - hsz;
        int blocks = (int)((tail + 255) / 256);
        zero_tail_kernel<<<blocks, 256>>>(out, hsz, (long long)out_size);
    }

    dim3 ggrid(BATCH * NNODE / 128, 4);
    float* hbuf[2] = { h0, h1 };
    for (int l = 0; l < 2; l++) {
        tgemm256<false, true><<<ggrid, 256>>>(hbuf[l], gat_w + (long long)l * DIM * DIM,
                                              nullptr, wh,
                                              gat_asrc + l * HEADS * 64,
                                              gat_adst + l * HEADS * 64, l);
        gat_attn_mma<<<dim3(4, HEADS, BATCH), 256>>>(wh, gat_b + l * DIM, hbuf[1 - l], l);
    }
    tgemm256<true, false><<<ggrid, 256>>>(h0, proj_w, proj_b, out, nullptr, nullptr, 0);
}

// round 12
// speedup vs baseline: 1.7933x; 1.1225x over previous
#include <cuda_runtime.h>
#include <cstdint>

#define BATCH 16
#define NNODE 1024
#define DIM 256
#define HEADS 4
#define NBR 1023
#define TSTEPS 20

// ---------------- scratch (device globals; no allocation allowed) ----------------
__device__ float g_h0[BATCH * NNODE * DIM];
__device__ float g_h1[BATCH * NNODE * DIM];
__device__ float g_wh[BATCH * NNODE * DIM];
__device__ float g_pos[BATCH * NNODE * 2];
__device__ float g_as[BATCH * HEADS * NNODE];
__device__ float g_ad[BATCH * HEADS * NNODE];
__device__ uint32_t g_asmaxu[2 * BATCH * HEADS];  // [layer][bh], order-preserving enc
__device__ uint32_t g_adjT[BATCH * 32 * NNODE];   // [b][jword][i] bit lane = j%32

// ======================= helpers =======================
__device__ __forceinline__ void mma_f16(float* c, uint32_t a0, uint32_t a1,
                                        uint32_t a2, uint32_t a3,
                                        uint32_t b0, uint32_t b1) {
    asm volatile(
        "mma.sync.aligned.m16n8k16.row.col.f32.f16.f16.f32 "
        "{%0,%1,%2,%3}, {%4,%5,%6,%7}, {%8,%9}, {%0,%1,%2,%3};"
        : "+f"(c[0]), "+f"(c[1]), "+f"(c[2]), "+f"(c[3])
        : "r"(a0), "r"(a1), "r"(a2), "r"(a3), "r"(b0), "r"(b1));
}
__device__ __forceinline__ float slctf(float a, float b, float c) {
    float d;
    asm("slct.f32.f32 %0, %1, %2, %3;" : "=f"(d) : "f"(a), "f"(b), "f"(c));
    return d;
}
__device__ __forceinline__ uint32_t pack2(float lo, float hi) {
    uint32_t d;
    asm("cvt.rn.f16x2.f32 %0, %1, %2;" : "=r"(d) : "f"(hi), "f"(lo));
    return d;
}
__device__ __forceinline__ uint32_t fenc(float f) {
    uint32_t b = __float_as_uint(f);
    return ((int)b < 0) ? ~b : (b | 0x80000000u);
}
__device__ __forceinline__ float fdec(uint32_t u) {
    return __uint_as_float((u & 0x80000000u) ? (u ^ 0x80000000u) : ~u);
}

// ---------------- embed: 8 nodes per block, weight col in regs ----------------
__global__ __launch_bounds__(256) void embed_kernel(
    const float* __restrict__ ego, const float* __restrict__ nbr,
    const float* __restrict__ node_w, const float* __restrict__ node_b,
    const float* __restrict__ node_g, const float* __restrict__ node_bb,
    const float* __restrict__ ego_w, const float* __restrict__ ego_b,
    const float* __restrict__ ego_g, const float* __restrict__ ego_bb)
{
    int t = threadIdx.x;
    int bn0 = blockIdx.x * 8;
    __shared__ float f[8][5];
    __shared__ float ws[8][8], wq[8][8];
    if (t < 40) {
        int nn = t / 5, k = t - nn * 5;
        int bn = bn0 + nn;
        int b = bn >> 10, n = bn & 1023;
        float v = (n == 0) ? ego[(b * TSTEPS + TSTEPS - 1) * 7 + k]
                           : nbr[((b * NBR + (n - 1)) * TSTEPS + TSTEPS - 1) * 11 + k];
        f[nn][k] = v;
        if (k < 2) g_pos[bn * 2 + k] = v;
    }
    __syncthreads();
    float wn[5];
#pragma unroll
    for (int k = 0; k < 5; k++) wn[k] = node_w[k * DIM + t];
    float nb = node_b[t];
    int lane = t & 31, w = t >> 5;
    float vv[8];
#pragma unroll
    for (int nn = 0; nn < 8; nn++) {
        int n = (bn0 + nn) & 1023;
        float v;
        if (n == 0) {
            v = ego_b[t];
#pragma unroll
            for (int k = 0; k < 5; k++) v = fmaf(f[nn][k], ego_w[k * DIM + t], v);
        } else {
            v = nb;
#pragma unroll
            for (int k = 0; k < 5; k++) v = fmaf(f[nn][k], wn[k], v);
        }
        v = fmaxf(v, 0.f);
        vv[nn] = v;
        float s = v, q = v * v;
#pragma unroll
        for (int o = 16; o; o >>= 1) {
            s += __shfl_down_sync(0xffffffffu, s, o);
            q += __shfl_down_sync(0xffffffffu, q, o);
        }
        if (lane == 0) { ws[nn][w] = s; wq[nn][w] = q; }
    }
    __syncthreads();
    float ng = node_g[t], nbb = node_bb[t];
#pragma unroll
    for (int nn = 0; nn < 8; nn++) {
        int bn = bn0 + nn;
        int n = bn & 1023;
        float sum = 0.f, sq = 0.f;
#pragma unroll
        for (int i = 0; i < 8; i++) { sum += ws[nn][i]; sq += wq[nn][i]; }
        float mean = sum * (1.f / 256.f);
        float var = fmaxf(sq * (1.f / 256.f) - mean * mean, 0.f);
        float inv = rsqrtf(var + 1e-5f);
        float gg = ng, bb2 = nbb;
        if (n == 0) { gg = ego_g[t]; bb2 = ego_bb[t]; }
        g_h0[(size_t)bn * DIM + t] = (vv[nn] - mean) * inv * gg + bb2;
    }
}

// ---------------- adjacency bitmask + asmax buffer init ----------------
__global__ __launch_bounds__(256) void adj_kernel()
{
    int b = blockIdx.z, jw = blockIdx.y;
    int lane = threadIdx.x & 31, w = threadIdx.x >> 5;
    if (blockIdx.x == 0 && jw == 0 && threadIdx.x < 8) {
        int l = threadIdx.x >> 2, h = threadIdx.x & 3;
        g_asmaxu[l * (BATCH * HEADS) + b * HEADS + h] = 0u;
    }
    int j = jw * 32 + lane;
    float2 pj = ((const float2*)g_pos)[b * NNODE + j];
    int i0 = blockIdx.x * 32 + w;
#pragma unroll
    for (int q = 0; q < 4; q++) {
        int i = i0 + q * 8;
        float2 pi = ((const float2*)g_pos)[b * NNODE + i];
        float dx = pj.x - pi.x, dy = pj.y - pi.y;
        bool a = (fmaf(dx, dx, dy * dy) < 2500.f) || (i == j);
        uint32_t word = __ballot_sync(0xffffffffu, a);
        if (lane == 0) g_adjT[(b * 32 + jw) * NNODE + i] = word;
    }
}

// ---------------- fp16 tensor-core GEMM (+fused a_src/a_dst + asmax) ----------
// A packed half2 along K: As_p[row][kp], stride 20 (conflict-free frag loads).
// B packed half2 along K: Bs_p[kp][n],  stride 72 (same pattern as attn, verified).
#define GA_STRIDE 20
#define GB_STRIDE 72
template <bool BIAS, bool SAD>
__global__ __launch_bounds__(256) void tgemm256(
    const float* __restrict__ A, const float* __restrict__ W,
    const float* __restrict__ bias, float* __restrict__ C,
    const float* __restrict__ asrc, const float* __restrict__ adst,
    int sadLayer)
{
    __shared__ uint32_t As_p[128 * GA_STRIDE];
    __shared__ uint32_t Bs_p[16 * GB_STRIDE];
    int tid = threadIdx.x, w = tid >> 5, lane = tid & 31;
    int g4 = lane >> 2, q4 = lane & 3;
    int m0 = blockIdx.x * 128, n0 = blockIdx.y * 64;
    int wm = w & 3, wn = w >> 2;
    int r0 = wm * 32, c0 = wn * 32;

    int af4 = tid & 7, arow = tid >> 3;          // A: rows arow+q*32, k = af4*4..+3
    int bf4 = tid & 15, brow = tid >> 4;         // B: k-rows 2*brow, 2*brow+1; n = bf4*4
    const float* Ag = A + (size_t)(m0 + arow) * 256 + af4 * 4;
    const float* Wg = W + (size_t)(2 * brow) * 256 + n0 + bf4 * 4;

    float acc[2][4][4];
#pragma unroll
    for (int mt = 0; mt < 2; mt++)
#pragma unroll
        for (int nt = 0; nt < 4; nt++)
#pragma unroll
            for (int k = 0; k < 4; k++) acc[mt][nt][k] = 0.f;

    float4 pa[4], pb[2];
#pragma unroll
    for (int q = 0; q < 4; q++) pa[q] = *(const float4*)(Ag + (size_t)q * 32 * 256);
    pb[0] = *(const float4*)Wg;
    pb[1] = *(const float4*)(Wg + 256);

    for (int kc = 0; kc < 8; kc++) {
        __syncthreads();
#pragma unroll
        for (int q = 0; q < 4; q++) {
            uint32_t* d = As_p + (arow + q * 32) * GA_STRIDE + af4 * 2;
            d[0] = pack2(pa[q].x, pa[q].y);
            d[1] = pack2(pa[q].z, pa[q].w);
        }
        {
            uint4 o;
            o.x = pack2(pb[0].x, pb[1].x);
            o.y = pack2(pb[0].y, pb[1].y);
            o.z = pack2(pb[0].z, pb[1].z);
            o.w = pack2(pb[0].w, pb[1].w);
            *(uint4*)&Bs_p[brow * GB_STRIDE + bf4 * 4] = o;
        }
        __syncthreads();
        if (kc < 7) {
            const float* Agn = Ag + (kc + 1) * 32;
            const float* Wgn = Wg + (size_t)(kc + 1) * 32 * 256;
#pragma unroll
            for (int q = 0; q < 4; q++) pa[q] = *(const float4*)(Agn + (size_t)q * 32 * 256);
            pb[0] = *(const float4*)Wgn;
            pb[1] = *(const float4*)(Wgn + 256);
        }
#pragma unroll
        for (int kbb = 0; kbb < 2; kbb++) {
            const uint32_t* ap = As_p + (r0 + g4) * GA_STRIDE + kbb * 8 + q4;
            uint32_t a00 = ap[0];
            uint32_t a01 = ap[8 * GA_STRIDE];
            uint32_t a02 = ap[4];
            uint32_t a03 = ap[8 * GA_STRIDE + 4];
            uint32_t a10 = ap[16 * GA_STRIDE];
            uint32_t a11 = ap[24 * GA_STRIDE];
            uint32_t a12 = ap[16 * GA_STRIDE + 4];
            uint32_t a13 = ap[24 * GA_STRIDE + 4];
            const uint32_t* bp = Bs_p + (kbb * 8 + q4) * GB_STRIDE + c0 + g4;
#pragma unroll
            for (int nt = 0; nt < 4; nt++) {
                uint32_t b0 = bp[nt * 8];
                uint32_t b1 = bp[nt * 8 + 4 * GB_STRIDE];
                mma_f16(acc[0][nt], a00, a01, a02, a03, b0, b1);
                mma_f16(acc[1][nt], a10, a11, a12, a13, b0, b1);
            }
        }
    }
    // ---- C store ----
#pragma unroll
    for (int mt = 0; mt < 2; mt++) {
        int row = m0 + r0 + mt * 16 + g4;
        float* c0p = C + (size_t)row * 256 + n0 + c0;
        float* c1p = c0p + 8 * 256;
#pragma unroll
        for (int nt = 0; nt < 4; nt++) {
            int cc = nt * 8 + q4 * 2;
            float bx = 0.f, by = 0.f;
            if (BIAS) { bx = bias[n0 + c0 + cc]; by = bias[n0 + c0 + cc + 1]; }
            float2 u0, u1;
            u0.x = acc[mt][nt][0] + bx; u0.y = acc[mt][nt][1] + by;
            u1.x = acc[mt][nt][2] + bx; u1.y = acc[mt][nt][3] + by;
            *(float2*)(c0p + cc) = u0;
            *(float2*)(c1p + cc) = u1;
        }
    }
    // ---- fused a_src / a_dst + asmax ----
    if (SAD) {
        float as_c[8], ad_c[8];
#pragma unroll
        for (int nt = 0; nt < 4; nt++) {
            int cg = n0 + c0 + nt * 8 + q4 * 2;
            as_c[nt * 2] = asrc[cg]; as_c[nt * 2 + 1] = asrc[cg + 1];
            ad_c[nt * 2] = adst[cg]; ad_c[nt * 2 + 1] = adst[cg + 1];
        }
        __syncthreads();
        float* red = (float*)As_p;
#pragma unroll
        for (int mt = 0; mt < 2; mt++) {
            float sAs = 0.f, sAd = 0.f, sBs = 0.f, sBd = 0.f;
#pragma unroll
            for (int nt = 0; nt < 4; nt++) {
                sAs += acc[mt][nt][0] * as_c[nt * 2] + acc[mt][nt][1] * as_c[nt * 2 + 1];
                sBs += acc[mt][nt][2] * as_c[nt * 2] + acc[mt][nt][3] * as_c[nt * 2 + 1];
                sAd += acc[mt][nt][0] * ad_c[nt * 2] + acc[mt][nt][1] * ad_c[nt * 2 + 1];
                sBd += acc[mt][nt][2] * ad_c[nt * 2] + acc[mt][nt][3] * ad_c[nt * 2 + 1];
            }
#pragma unroll
            for (int o = 1; o < 4; o <<= 1) {
                sAs += __shfl_xor_sync(0xffffffffu, sAs, o);
                sAd += __shfl_xor_sync(0xffffffffu, sAd, o);
                sBs += __shfl_xor_sync(0xffffffffu, sBs, o);
                sBd += __shfl_xor_sync(0xffffffffu, sBd, o);
            }
            if (q4 == 0) {
                int rA = r0 + mt * 16 + g4, rB = rA + 8;
                *(float2*)&red[(rA * 2 + wn) * 2] = make_float2(sAs, sAd);
                *(float2*)&red[(rB * 2 + wn) * 2] = make_float2(sBs, sBd);
            }
        }
        __syncthreads();
        if (tid < 128) {
            float2 v0 = *(float2*)&red[(tid * 2 + 0) * 2];
            float2 v1 = *(float2*)&red[(tid * 2 + 1) * 2];
            int b = m0 >> 10, n = (m0 & 1023) + tid;
            int bh = b * HEADS + blockIdx.y;
            float asv = v0.x + v1.x;
            g_as[bh * NNODE + n] = asv;
            g_ad[bh * NNODE + n] = v0.y + v1.y;
            float m = asv;
#pragma unroll
            for (int o = 16; o; o >>= 1)
                m = fmaxf(m, __shfl_xor_sync(0xffffffffu, m, o));
            if (lane == 0)
                atomicMax(&g_asmaxu[sadLayer * (BATCH * HEADS) + bh], fenc(m));
        }
    }
}

// ---------------- GAT attention: fp16 m16n8k16 MMA, register-P, adj fast path ----
#define VP_STRIDE 72
__global__ __launch_bounds__(256, 2) void gat_attn_mma(
    const float* __restrict__ wh, const float* __restrict__ gbias,
    float* __restrict__ hout, int layer)
{
    __shared__ uint32_t v_p[32 * VP_STRIDE];
    __shared__ float4 je[64];            // (as_j, E1_j, E2_j, -)
    __shared__ uint32_t adj_sm[512];

    int tid = threadIdx.x, w = tid >> 5, lane = tid & 31;
    int g4 = lane >> 2, q4 = lane & 3;
    int it = blockIdx.x, hh = blockIdx.y, b = blockIdx.z;
    int i0 = it * 256, bh = b * HEADS + hh;
    int r0 = w * 32;

    float F1[4], F2[4], adreg[4];
    {
        float mx = fdec(g_asmaxu[layer * (BATCH * HEADS) + bh]);
#pragma unroll
        for (int t = 0; t < 4; t++) {
            float ad = g_ad[bh * NNODE + i0 + r0 + t * 8 + g4];
            adreg[t] = ad;
            float mm = mx + ad;
            float mr = fmaxf(mm, 0.2f * mm);
            F1[t] = __expf(ad - mr);
            F2[t] = __expf(0.2f * ad - mr);
        }
    }
    {
        int jp = tid >> 3, cc = 64 + (tid & 7);
        v_p[jp * VP_STRIDE + cc] = (cc == 64) ? 0x3C003C00u : 0u;
    }

    float acc[2][9][4];
#pragma unroll
    for (int mt = 0; mt < 2; mt++)
#pragma unroll
        for (int n = 0; n < 9; n++)
#pragma unroll
            for (int k = 0; k < 4; k++) acc[mt][n][k] = 0.f;

    const float* whb = wh + ((size_t)(b * NNODE)) * DIM + hh * 64;
    const uint32_t* adjb = g_adjT + (size_t)b * 32 * NNODE + i0;

    for (int ch = 0; ch < 16; ch++) {
        int j0c = ch * 64;
        __syncthreads();
        {
            int jp = tid >> 3, cb = (tid & 7) * 8;
            const float* rA = whb + (size_t)(j0c + 2 * jp) * DIM + cb;
            const float* rB = rA + DIM;
            float4 a0 = *(const float4*)rA, a1 = *(const float4*)(rA + 4);
            float4 b0 = *(const float4*)rB, b1 = *(const float4*)(rB + 4);
            uint4 o0, o1;
            o0.x = pack2(a0.x, b0.x); o0.y = pack2(a0.y, b0.y);
            o0.z = pack2(a0.z, b0.z); o0.w = pack2(a0.w, b0.w);
            o1.x = pack2(a1.x, b1.x); o1.y = pack2(a1.y, b1.y);
            o1.z = pack2(a1.z, b1.z); o1.w = pack2(a1.w, b1.w);
            *(uint4*)&v_p[jp * VP_STRIDE + cb] = o0;
            *(uint4*)&v_p[jp * VP_STRIDE + cb + 4] = o1;
        }
        if (tid < 64) {
            float a = g_as[bh * NNODE + j0c + tid];
            je[tid] = make_float4(a, __expf(a), __expf(0.2f * a), 0.f);
        }
        adj_sm[tid] = adjb[(size_t)(2 * ch) * NNODE + tid];
        adj_sm[256 + tid] = adjb[(size_t)(2 * ch + 1) * NNODE + tid];
        __syncthreads();
        uint32_t Aw[2][4];
#pragma unroll
        for (int t = 0; t < 4; t++) {
            Aw[0][t] = adj_sm[r0 + t * 8 + g4];
            Aw[1][t] = adj_sm[256 + r0 + t * 8 + g4];
        }
        uint32_t andall = Aw[0][0] & Aw[0][1] & Aw[0][2] & Aw[0][3]
                        & Aw[1][0] & Aw[1][1] & Aw[1][2] & Aw[1][3];
        bool allones = __all_sync(0xffffffffu, andall == 0xffffffffu);

#pragma unroll
        for (int kb = 0; kb < 4; kb++) {
            int jlo = kb * 16 + 2 * q4;
            float4 jeA = je[jlo];
            float4 jeB = je[jlo + 1];
            float4 jeC = je[jlo + 8];
            float4 jeD = je[jlo + 9];
            uint32_t afr[2][4];
            if (allones) {
#pragma unroll
                for (int t = 0; t < 4; t++) {
                    float pa = slctf(jeA.y * F1[t], jeA.z * F2[t], jeA.x + adreg[t]);
                    float pb = slctf(jeB.y * F1[t], jeB.z * F2[t], jeB.x + adreg[t]);
                    float pc = slctf(jeC.y * F1[t], jeC.z * F2[t], jeC.x + adreg[t]);
                    float pd = slctf(jeD.y * F1[t], jeD.z * F2[t], jeD.x + adreg[t]);
                    afr[t >> 1][t & 1] = pack2(pa, pb);
                    afr[t >> 1][2 + (t & 1)] = pack2(pc, pd);
                }
            } else {
                int half = kb >> 1;
                int s = jlo & 31;
#pragma unroll
                for (int t = 0; t < 4; t++) {
                    uint32_t wv = Aw[half][t];
                    uint32_t b2lo = (wv >> s) & 3u;
                    uint32_t b2hi = (wv >> (s + 8)) & 3u;
                    uint32_t mlo = ((b2lo & 1u) ? 0x0000FFFFu : 0u) |
                                   ((b2lo & 2u) ? 0xFFFF0000u : 0u);
                    uint32_t mhi = ((b2hi & 1u) ? 0x0000FFFFu : 0u) |
                                   ((b2hi & 2u) ? 0xFFFF0000u : 0u);
                    float pa = slctf(jeA.y * F1[t], jeA.z * F2[t], jeA.x + adreg[t]);
                    float pb = slctf(jeB.y * F1[t], jeB.z * F2[t], jeB.x + adreg[t]);
                    float pc = slctf(jeC.y * F1[t], jeC.z * F2[t], jeC.x + adreg[t]);
                    float pd = slctf(jeD.y * F1[t], jeD.z * F2[t], jeD.x + adreg[t]);
                    afr[t >> 1][t & 1] = pack2(pa, pb) & mlo;
                    afr[t >> 1][2 + (t & 1)] = pack2(pc, pd) & mhi;
                }
            }
            const uint32_t* bp = v_p + (kb * 8 + q4) * VP_STRIDE + g4;
#pragma unroll
            for (int nt = 0; nt < 9; nt++) {
                uint32_t b0 = bp[nt * 8];
                uint32_t b1 = bp[nt * 8 + 4 * VP_STRIDE];
                mma_f16(acc[0][nt], afr[0][0], afr[0][1], afr[0][2], afr[0][3], b0, b1);
                mma_f16(acc[1][nt], afr[1][0], afr[1][1], afr[1][2], afr[1][3], b0, b1);
            }
        }
    }
    const float* bp = gbias + hh * 64;
#pragma unroll
    for (int mt = 0; mt < 2; mt++) {
        float z0 = __shfl_sync(0xffffffffu, acc[mt][8][0], lane & 28);
        float z1 = __shfl_sync(0xffffffffu, acc[mt][8][2], lane & 28);
        float iz0 = 1.f / z0;
        float iz1 = 1.f / z1;
        int rowg = i0 + r0 + mt * 16 + g4;
        float* o0 = hout + ((size_t)(b * NNODE) + rowg) * DIM + hh * 64;
        float* o1 = o0 + 8 * DIM;
#pragma unroll
        for (int nt = 0; nt < 8; nt++) {
            int cc = nt * 8 + q4 * 2;
            float bx = bp[cc], by = bp[cc + 1];
            float2 u0, u1;
            u0.x = fmaxf(fmaf(acc[mt][nt][0], iz0, bx), 0.f);
            u0.y = fmaxf(fmaf(acc[mt][nt][1], iz0, by), 0.f);
            u1.x = fmaxf(fmaf(acc[mt][nt][2], iz1, bx), 0.f);
            u1.y = fmaxf(fmaf(acc[mt][nt][3], iz1, by), 0.f);
            *(float2*)(o0 + cc) = u0;
            *(float2*)(o1 + cc) = u1;
        }
    }
}

// ---------------- zero tail of output (mask = all false) ----------------
__global__ void zero_tail_kernel(float* out, long long start, long long total)
{
    long long i = start + (long long)blockIdx.x * blockDim.x + threadIdx.x;
    if (i < total) out[i] = 0.f;
}

// ---------------- launch ----------------
extern "C" void kernel_launch(void* const* d_in, const int* in_sizes, int n_in,
                              void* d_out, int out_size)
{
    const float* ego      = (const float*)d_in[0];
    const float* nbr      = (const float*)d_in[1];
    const float* node_w   = (const float*)d_in[2];
    const float* node_b   = (const float*)d_in[3];
    const float* node_g   = (const float*)d_in[4];
    const float* node_bb  = (const float*)d_in[5];
    const float* ego_w    = (const float*)d_in[6];
    const float* ego_b    = (const float*)d_in[7];
    const float* ego_g    = (const float*)d_in[8];
    const float* ego_bb   = (const float*)d_in[9];
    const float* gat_w    = (const float*)d_in[10];
    const float* gat_asrc = (const float*)d_in[11];
    const float* gat_adst = (const float*)d_in[12];
    const float* gat_b    = (const float*)d_in[13];
    const float* proj_w   = (const float*)d_in[14];
    const float* proj_b   = (const float*)d_in[15];
    float* out = (float*)d_out;

    float *h0, *h1, *wh;
    cudaGetSymbolAddress((void**)&h0, g_h0);
    cudaGetSymbolAddress((void**)&h1, g_h1);
    cudaGetSymbolAddress((void**)&wh, g_wh);

    embed_kernel<<<BATCH * NNODE / 8, 256>>>(ego, nbr, node_w, node_b, node_g, node_bb,
                                             ego_w, ego_b, ego_g, ego_bb);
    adj_kernel<<<dim3(NNODE / 32, 32, BATCH), 256>>>();

    long long hsz = (long long)BATCH * NNODE * DIM;
    if ((long long)out_size > hsz) {
        long long tail = (long long)out_size - hsz;
        int blocks = (int)((tail + 255) / 256);
        zero_tail_kernel<<<blocks, 256>>>(out, hsz, (long long)out_size);
    }

    dim3 ggrid(BATCH * NNODE / 128, 4);
    float* hbuf[2] = { h0, h1 };
    for (int l = 0; l < 2; l++) {
        tgemm256<false, true><<<ggrid, 256>>>(hbuf[l], gat_w + (long long)l * DIM * DIM,
                                              nullptr, wh,
                                              gat_asrc + l * HEADS * 64,
                                              gat_adst + l * HEADS * 64, l);
        gat_attn_mma<<<dim3(4, HEADS, BATCH), 256>>>(wh, gat_b + l * DIM, hbuf[1 - l], l);
    }
    tgemm256<true, false><<<ggrid, 256>>>(h0, proj_w, proj_b, out, nullptr, nullptr, 0);
}

// round 13
// speedup vs baseline: 1.9006x; 1.0598x over previous
#include <cuda_runtime.h>
#include <cuda_fp16.h>
#include <cstdint>

#define BATCH 16
#define NNODE 1024
#define DIM 256
#define HEADS 4
#define NBR 1023
#define TSTEPS 20

// ---------------- scratch (device globals; no allocation allowed) ----------------
__device__ __half g_h0h[BATCH * NNODE * DIM];     // h buffers, fp16 row-major
__device__ __half g_h1h[BATCH * NNODE * DIM];
__device__ __half g_whh[BATCH * NNODE * DIM];     // wh, fp16 row-major
__device__ uint32_t g_wpack[3 * 128 * 256];       // weights K-pair-packed half2
__device__ float g_pos[BATCH * NNODE * 2];
__device__ float g_as[BATCH * HEADS * NNODE];
__device__ float g_ad[BATCH * HEADS * NNODE];
__device__ uint32_t g_asmaxu[2 * BATCH * HEADS];
__device__ uint32_t g_adjT[BATCH * 32 * NNODE];

// ======================= helpers =======================
__device__ __forceinline__ void mma_f16(float* c, uint32_t a0, uint32_t a1,
                                        uint32_t a2, uint32_t a3,
                                        uint32_t b0, uint32_t b1) {
    asm volatile(
        "mma.sync.aligned.m16n8k16.row.col.f32.f16.f16.f32 "
        "{%0,%1,%2,%3}, {%4,%5,%6,%7}, {%8,%9}, {%0,%1,%2,%3};"
        : "+f"(c[0]), "+f"(c[1]), "+f"(c[2]), "+f"(c[3])
        : "r"(a0), "r"(a1), "r"(a2), "r"(a3), "r"(b0), "r"(b1));
}
__device__ __forceinline__ float slctf(float a, float b, float c) {
    float d;
    asm("slct.f32.f32 %0, %1, %2, %3;" : "=f"(d) : "f"(a), "f"(b), "f"(c));
    return d;
}
__device__ __forceinline__ uint32_t pack2(float lo, float hi) {
    uint32_t d;
    asm("cvt.rn.f16x2.f32 %0, %1, %2;" : "=r"(d) : "f"(hi), "f"(lo));
    return d;
}
__device__ __forceinline__ uint32_t prmtb(uint32_t a, uint32_t b, uint32_t s) {
    uint32_t d;
    asm("prmt.b32 %0, %1, %2, %3;" : "=r"(d) : "r"(a), "r"(b), "r"(s));
    return d;
}
__device__ __forceinline__ uint32_t fenc(float f) {
    uint32_t b = __float_as_uint(f);
    return ((int)b < 0) ? ~b : (b | 0x80000000u);
}
__device__ __forceinline__ float fdec(uint32_t u) {
    return __uint_as_float((u & 0x80000000u) ? (u ^ 0x80000000u) : ~u);
}

// ---------------- weight prep: pack K-pairs to half2 ----------------
__global__ __launch_bounds__(256) void wprep_kernel(
    const float* __restrict__ gat_w, const float* __restrict__ proj_w)
{
    int wsel = blockIdx.x >> 7;          // 0,1 = gat layers; 2 = proj
    int kp = blockIdx.x & 127;
    int n = threadIdx.x;
    const float* W = (wsel < 2) ? gat_w + (size_t)wsel * 65536 : proj_w;
    float lo = W[(size_t)(2 * kp) * 256 + n];
    float hi = W[(size_t)(2 * kp + 1) * 256 + n];
    g_wpack[(size_t)wsel * 32768 + kp * 256 + n] = pack2(lo, hi);
}

// ---------------- embed: 8 nodes per block, fp16 output ----------------
__global__ __launch_bounds__(256) void embed_kernel(
    const float* __restrict__ ego, const float* __restrict__ nbr,
    const float* __restrict__ node_w, const float* __restrict__ node_b,
    const float* __restrict__ node_g, const float* __restrict__ node_bb,
    const float* __restrict__ ego_w, const float* __restrict__ ego_b,
    const float* __restrict__ ego_g, const float* __restrict__ ego_bb)
{
    int t = threadIdx.x;
    int bn0 = blockIdx.x * 8;
    __shared__ float f[8][5];
    __shared__ float ws[8][8], wq[8][8];
    if (t < 40) {
        int nn = t / 5, k = t - nn * 5;
        int bn = bn0 + nn;
        int b = bn >> 10, n = bn & 1023;
        float v = (n == 0) ? ego[(b * TSTEPS + TSTEPS - 1) * 7 + k]
                           : nbr[((b * NBR + (n - 1)) * TSTEPS + TSTEPS - 1) * 11 + k];
        f[nn][k] = v;
        if (k < 2) g_pos[bn * 2 + k] = v;
    }
    __syncthreads();
    float wn[5];
#pragma unroll
    for (int k = 0; k < 5; k++) wn[k] = node_w[k * DIM + t];
    float nb = node_b[t];
    int lane = t & 31, w = t >> 5;
    float vv[8];
#pragma unroll
    for (int nn = 0; nn < 8; nn++) {
        int n = (bn0 + nn) & 1023;
        float v;
        if (n == 0) {
            v = ego_b[t];
#pragma unroll
            for (int k = 0; k < 5; k++) v = fmaf(f[nn][k], ego_w[k * DIM + t], v);
        } else {
            v = nb;
#pragma unroll
            for (int k = 0; k < 5; k++) v = fmaf(f[nn][k], wn[k], v);
        }
        v = fmaxf(v, 0.f);
        vv[nn] = v;
        float s = v, q = v * v;
#pragma unroll
        for (int o = 16; o; o >>= 1) {
            s += __shfl_down_sync(0xffffffffu, s, o);
            q += __shfl_down_sync(0xffffffffu, q, o);
        }
        if (lane == 0) { ws[nn][w] = s; wq[nn][w] = q; }
    }
    __syncthreads();
    float ng = node_g[t], nbb = node_bb[t];
#pragma unroll
    for (int nn = 0; nn < 8; nn++) {
        int bn = bn0 + nn;
        int n = bn & 1023;
        float sum = 0.f, sq = 0.f;
#pragma unroll
        for (int i = 0; i < 8; i++) { sum += ws[nn][i]; sq += wq[nn][i]; }
        float mean = sum * (1.f / 256.f);
        float var = fmaxf(sq * (1.f / 256.f) - mean * mean, 0.f);
        float inv = rsqrtf(var + 1e-5f);
        float gg = ng, bb2 = nbb;
        if (n == 0) { gg = ego_g[t]; bb2 = ego_bb[t]; }
        g_h0h[(size_t)bn * DIM + t] = __float2half_rn((vv[nn] - mean) * inv * gg + bb2);
    }
}

// ---------------- adjacency bitmask + asmax buffer init ----------------
__global__ __launch_bounds__(256) void adj_kernel()
{
    int b = blockIdx.z, jw = blockIdx.y;
    int lane = threadIdx.x & 31, w = threadIdx.x >> 5;
    if (blockIdx.x == 0 && jw == 0 && threadIdx.x < 8) {
        int l = threadIdx.x >> 2, h = threadIdx.x & 3;
        g_asmaxu[l * (BATCH * HEADS) + b * HEADS + h] = 0u;
    }
    int j = jw * 32 + lane;
    float2 pj = ((const float2*)g_pos)[b * NNODE + j];
    int i0 = blockIdx.x * 32 + w;
#pragma unroll
    for (int q = 0; q < 4; q++) {
        int i = i0 + q * 8;
        float2 pi = ((const float2*)g_pos)[b * NNODE + i];
        float dx = pj.x - pi.x, dy = pj.y - pi.y;
        bool a = (fmaf(dx, dx, dy * dy) < 2500.f) || (i == j);
        uint32_t word = __ballot_sync(0xffffffffu, a);
        if (lane == 0) g_adjT[(b * 32 + jw) * NNODE + i] = word;
    }
}

// ---------------- fp16 tensor-core GEMM, fp16 operands from gmem ----------
// A_pack: [M][128] uint32 = row-major halves of A. W_pack: [128][256] uint32.
#define GA_STRIDE 20
#define GB_STRIDE 72
template <bool BIAS, bool SAD>
__global__ __launch_bounds__(256) void tgemm256(
    const uint32_t* __restrict__ A_pack, const uint32_t* __restrict__ W_pack,
    const float* __restrict__ bias, float* __restrict__ Cf, __half* __restrict__ Ch,
    const float* __restrict__ asrc, const float* __restrict__ adst,
    int sadLayer)
{
    __shared__ uint32_t As_p[128 * GA_STRIDE];
    __shared__ uint32_t Bs_p[16 * GB_STRIDE];
    int tid = threadIdx.x, w = tid >> 5, lane = tid & 31;
    int g4 = lane >> 2, q4 = lane & 3;
    int m0 = blockIdx.x * 128, n0 = blockIdx.y * 64;
    int wm = w & 3, wn = w >> 2;
    int r0 = wm * 32, c0 = wn * 32;

    int arow = tid >> 2, af4 = tid & 3;          // A: rows arow, arow+64; kp f4*4..+3
    int brow = tid >> 4, bf4 = tid & 15;         // B: kp-row brow; n bf4*4..+3
    const uint4* Ag = (const uint4*)(A_pack + (size_t)(m0 + arow) * 128 + af4 * 4);
    const uint4* Wg = (const uint4*)(W_pack + (size_t)brow * 256 + n0 + bf4 * 4);

    float acc[2][4][4];
#pragma unroll
    for (int mt = 0; mt < 2; mt++)
#pragma unroll
        for (int nt = 0; nt < 4; nt++)
#pragma unroll
            for (int k = 0; k < 4; k++) acc[mt][nt][k] = 0.f;

    uint4 pa0 = Ag[0];
    uint4 pa1 = Ag[(size_t)64 * 32];             // row+64: 64*128/4 uint4
    uint4 pb0 = Wg[0];

    for (int kc = 0; kc < 8; kc++) {
        __syncthreads();
        *(uint4*)&As_p[arow * GA_STRIDE + af4 * 4] = pa0;
        *(uint4*)&As_p[(arow + 64) * GA_STRIDE + af4 * 4] = pa1;
        *(uint4*)&Bs_p[brow * GB_STRIDE + bf4 * 4] = pb0;
        __syncthreads();
        if (kc < 7) {
            const uint4* Agn = (const uint4*)((const uint32_t*)Ag + (kc + 1) * 16);
            const uint4* Wgn = (const uint4*)((const uint32_t*)Wg + (size_t)(kc + 1) * 16 * 256);
            pa0 = Agn[0];
            pa1 = Agn[(size_t)64 * 32];
            pb0 = Wgn[0];
        }
#pragma unroll
        for (int kbb = 0; kbb < 2; kbb++) {
            const uint32_t* ap = As_p + (r0 + g4) * GA_STRIDE + kbb * 8 + q4;
            uint32_t a00 = ap[0];
            uint32_t a01 = ap[8 * GA_STRIDE];
            uint32_t a02 = ap[4];
            uint32_t a03 = ap[8 * GA_STRIDE + 4];
            uint32_t a10 = ap[16 * GA_STRIDE];
            uint32_t a11 = ap[24 * GA_STRIDE];
            uint32_t a12 = ap[16 * GA_STRIDE + 4];
            uint32_t a13 = ap[24 * GA_STRIDE + 4];
            const uint32_t* bp = Bs_p + (kbb * 8 + q4) * GB_STRIDE + c0 + g4;
#pragma unroll
            for (int nt = 0; nt < 4; nt++) {
                uint32_t b0 = bp[nt * 8];
                uint32_t b1 = bp[nt * 8 + 4 * GB_STRIDE];
                mma_f16(acc[0][nt], a00, a01, a02, a03, b0, b1);
                mma_f16(acc[1][nt], a10, a11, a12, a13, b0, b1);
            }
        }
    }
    // ---- C store: fp32 (proj) or fp16 (wh) ----
#pragma unroll
    for (int mt = 0; mt < 2; mt++) {
        int row = m0 + r0 + mt * 16 + g4;
#pragma unroll
        for (int nt = 0; nt < 4; nt++) {
            int cc = nt * 8 + q4 * 2;
            if (BIAS) {
                float bx = bias[n0 + c0 + cc], by = bias[n0 + c0 + cc + 1];
                float2 u0, u1;
                u0.x = acc[mt][nt][0] + bx; u0.y = acc[mt][nt][1] + by;
                u1.x = acc[mt][nt][2] + bx; u1.y = acc[mt][nt][3] + by;
                *(float2*)&Cf[(size_t)row * 256 + n0 + c0 + cc] = u0;
                *(float2*)&Cf[(size_t)(row + 8) * 256 + n0 + c0 + cc] = u1;
            } else {
                *(uint32_t*)&Ch[(size_t)row * 256 + n0 + c0 + cc] =
                    pack2(acc[mt][nt][0], acc[mt][nt][1]);
                *(uint32_t*)&Ch[(size_t)(row + 8) * 256 + n0 + c0 + cc] =
                    pack2(acc[mt][nt][2], acc[mt][nt][3]);
            }
        }
    }
    // ---- fused a_src / a_dst + asmax ----
    if (SAD) {
        float as_c[8], ad_c[8];
#pragma unroll
        for (int nt = 0; nt < 4; nt++) {
            int cg = n0 + c0 + nt * 8 + q4 * 2;
            as_c[nt * 2] = asrc[cg]; as_c[nt * 2 + 1] = asrc[cg + 1];
            ad_c[nt * 2] = adst[cg]; ad_c[nt * 2 + 1] = adst[cg + 1];
        }
        __syncthreads();
        float* red = (float*)As_p;
#pragma unroll
        for (int mt = 0; mt < 2; mt++) {
            float sAs = 0.f, sAd = 0.f, sBs = 0.f, sBd = 0.f;
#pragma unroll
            for (int nt = 0; nt < 4; nt++) {
                sAs += acc[mt][nt][0] * as_c[nt * 2] + acc[mt][nt][1] * as_c[nt * 2 + 1];
                sBs += acc[mt][nt][2] * as_c[nt * 2] + acc[mt][nt][3] * as_c[nt * 2 + 1];
                sAd += acc[mt][nt][0] * ad_c[nt * 2] + acc[mt][nt][1] * ad_c[nt * 2 + 1];
                sBd += acc[mt][nt][2] * ad_c[nt * 2] + acc[mt][nt][3] * ad_c[nt * 2 + 1];
            }
#pragma unroll
            for (int o = 1; o < 4; o <<= 1) {
                sAs += __shfl_xor_sync(0xffffffffu, sAs, o);
                sAd += __shfl_xor_sync(0xffffffffu, sAd, o);
                sBs += __shfl_xor_sync(0xffffffffu, sBs, o);
                sBd += __shfl_xor_sync(0xffffffffu, sBd, o);
            }
            if (q4 == 0) {
                int rA = r0 + mt * 16 + g4, rB = rA + 8;
                *(float2*)&red[(rA * 2 + wn) * 2] = make_float2(sAs, sAd);
                *(float2*)&red[(rB * 2 + wn) * 2] = make_float2(sBs, sBd);
            }
        }
        __syncthreads();
        if (tid < 128) {
            float2 v0 = *(float2*)&red[(tid * 2 + 0) * 2];
            float2 v1 = *(float2*)&red[(tid * 2 + 1) * 2];
            int b = m0 >> 10, n = (m0 & 1023) + tid;
            int bh = b * HEADS + blockIdx.y;
            float asv = v0.x + v1.x;
            g_as[bh * NNODE + n] = asv;
            g_ad[bh * NNODE + n] = v0.y + v1.y;
            float m = asv;
#pragma unroll
            for (int o = 16; o; o >>= 1)
                m = fmaxf(m, __shfl_xor_sync(0xffffffffu, m, o));
            if (lane == 0)
                atomicMax(&g_asmaxu[sadLayer * (BATCH * HEADS) + bh], fenc(m));
        }
    }
}

// ---------------- GAT attention: fp16 m16n8k16 MMA, fp16 wh input ----
#define VP_STRIDE 72
__global__ __launch_bounds__(256, 2) void gat_attn_mma(
    const __half* __restrict__ whh, const float* __restrict__ gbias,
    __half* __restrict__ hout, int layer)
{
    __shared__ uint32_t v_p[32 * VP_STRIDE];
    __shared__ float4 je[64];
    __shared__ uint32_t adj_sm[512];

    int tid = threadIdx.x, w = tid >> 5, lane = tid & 31;
    int g4 = lane >> 2, q4 = lane & 3;
    int it = blockIdx.x, hh = blockIdx.y, b = blockIdx.z;
    int i0 = it * 256, bh = b * HEADS + hh;
    int r0 = w * 32;

    float F1[4], F2[4], adreg[4];
    {
        float mx = fdec(g_asmaxu[layer * (BATCH * HEADS) + bh]);
#pragma unroll
        for (int t = 0; t < 4; t++) {
            float ad = g_ad[bh * NNODE + i0 + r0 + t * 8 + g4];
            adreg[t] = ad;
            float mm = mx + ad;
            float mr = fmaxf(mm, 0.2f * mm);
            F1[t] = __expf(ad - mr);
            F2[t] = __expf(0.2f * ad - mr);
        }
    }
    {
        int jp = tid >> 3, cc = 64 + (tid & 7);
        v_p[jp * VP_STRIDE + cc] = (cc == 64) ? 0x3C003C00u : 0u;
    }

    float acc[2][9][4];
#pragma unroll
    for (int mt = 0; mt < 2; mt++)
#pragma unroll
        for (int n = 0; n < 9; n++)
#pragma unroll
            for (int k = 0; k < 4; k++) acc[mt][n][k] = 0.f;

    const __half* whb = whh + ((size_t)(b * NNODE)) * DIM + hh * 64;
    const uint32_t* adjb = g_adjT + (size_t)b * 32 * NNODE + i0;

    for (int ch = 0; ch < 16; ch++) {
        int j0c = ch * 64;
        __syncthreads();
        // fill v_p: interleave j-row pairs via prmt (fp16 source)
        {
            int jp = tid >> 3, cb = (tid & 7) * 8;
            const uint4* rA = (const uint4*)(whb + (size_t)(j0c + 2 * jp) * DIM + cb);
            const uint4* rB = (const uint4*)(whb + (size_t)(j0c + 2 * jp + 1) * DIM + cb);
            uint4 a = rA[0], bb4 = rB[0];
            uint4 o0, o1;
            o0.x = prmtb(a.x, bb4.x, 0x5410); o0.y = prmtb(a.x, bb4.x, 0x7632);
            o0.z = prmtb(a.y, bb4.y, 0x5410); o0.w = prmtb(a.y, bb4.y, 0x7632);
            o1.x = prmtb(a.z, bb4.z, 0x5410); o1.y = prmtb(a.z, bb4.z, 0x7632);
            o1.z = prmtb(a.w, bb4.w, 0x5410); o1.w = prmtb(a.w, bb4.w, 0x7632);
            *(uint4*)&v_p[jp * VP_STRIDE + cb] = o0;
            *(uint4*)&v_p[jp * VP_STRIDE + cb + 4] = o1;
        }
        if (tid < 64) {
            float a = g_as[bh * NNODE + j0c + tid];
            je[tid] = make_float4(a, __expf(a), __expf(0.2f * a), 0.f);
        }
        adj_sm[tid] = adjb[(size_t)(2 * ch) * NNODE + tid];
        adj_sm[256 + tid] = adjb[(size_t)(2 * ch + 1) * NNODE + tid];
        __syncthreads();
        uint32_t Aw[2][4];
#pragma unroll
        for (int t = 0; t < 4; t++) {
            Aw[0][t] = adj_sm[r0 + t * 8 + g4];
            Aw[1][t] = adj_sm[256 + r0 + t * 8 + g4];
        }
        uint32_t andall = Aw[0][0] & Aw[0][1] & Aw[0][2] & Aw[0][3]
                        & Aw[1][0] & Aw[1][1] & Aw[1][2] & Aw[1][3];
        bool allones = __all_sync(0xffffffffu, andall == 0xffffffffu);

#pragma unroll
        for (int kb = 0; kb < 4; kb++) {
            int jlo = kb * 16 + 2 * q4;
            float4 jeA = je[jlo];
            float4 jeB = je[jlo + 1];
            float4 jeC = je[jlo + 8];
            float4 jeD = je[jlo + 9];
            uint32_t afr[2][4];
            if (allones) {
#pragma unroll
                for (int t = 0; t < 4; t++) {
                    float pa = slctf(jeA.y * F1[t], jeA.z * F2[t], jeA.x + adreg[t]);
                    float pb = slctf(jeB.y * F1[t], jeB.z * F2[t], jeB.x + adreg[t]);
                    float pc = slctf(jeC.y * F1[t], jeC.z * F2[t], jeC.x + adreg[t]);
                    float pd = slctf(jeD.y * F1[t], jeD.z * F2[t], jeD.x + adreg[t]);
                    afr[t >> 1][t & 1] = pack2(pa, pb);
                    afr[t >> 1][2 + (t & 1)] = pack2(pc, pd);
                }
            } else {
                int half = kb >> 1;
                int s = jlo & 31;
#pragma unroll
                for (int t = 0; t < 4; t++) {
                    uint32_t wv = Aw[half][t];
                    uint32_t b2lo = (wv >> s) & 3u;
                    uint32_t b2hi = (wv >> (s + 8)) & 3u;
                    uint32_t mlo = ((b2lo & 1u) ? 0x0000FFFFu : 0u) |
                                   ((b2lo & 2u) ? 0xFFFF0000u : 0u);
                    uint32_t mhi = ((b2hi & 1u) ? 0x0000FFFFu : 0u) |
                                   ((b2hi & 2u) ? 0xFFFF0000u : 0u);
                    float pa = slctf(jeA.y * F1[t], jeA.z * F2[t], jeA.x + adreg[t]);
                    float pb = slctf(jeB.y * F1[t], jeB.z * F2[t], jeB.x + adreg[t]);
                    float pc = slctf(jeC.y * F1[t], jeC.z * F2[t], jeC.x + adreg[t]);
                    float pd = slctf(jeD.y * F1[t], jeD.z * F2[t], jeD.x + adreg[t]);
                    afr[t >> 1][t & 1] = pack2(pa, pb) & mlo;
                    afr[t >> 1][2 + (t & 1)] = pack2(pc, pd) & mhi;
                }
            }
            const uint32_t* bp = v_p + (kb * 8 + q4) * VP_STRIDE + g4;
#pragma unroll
            for (int nt = 0; nt < 9; nt++) {
                uint32_t b0 = bp[nt * 8];
                uint32_t b1 = bp[nt * 8 + 4 * VP_STRIDE];
                mma_f16(acc[0][nt], afr[0][0], afr[0][1], afr[0][2], afr[0][3], b0, b1);
                mma_f16(acc[1][nt], afr[1][0], afr[1][1], afr[1][2], afr[1][3], b0, b1);
            }
        }
    }
    const float* bp = gbias + hh * 64;
#pragma unroll
    for (int mt = 0; mt < 2; mt++) {
        float z0 = __shfl_sync(0xffffffffu, acc[mt][8][0], lane & 28);
        float z1 = __shfl_sync(0xffffffffu, acc[mt][8][2], lane & 28);
        float iz0 = 1.f / z0;
        float iz1 = 1.f / z1;
        int rowg = i0 + r0 + mt * 16 + g4;
        __half* o0 = hout + ((size_t)(b * NNODE) + rowg) * DIM + hh * 64;
        __half* o1 = o0 + 8 * DIM;
#pragma unroll
        for (int nt = 0; nt < 8; nt++) {
            int cc = nt * 8 + q4 * 2;
            float bx = bp[cc], by = bp[cc + 1];
            float u0x = fmaxf(fmaf(acc[mt][nt][0], iz0, bx), 0.f);
            float u0y = fmaxf(fmaf(acc[mt][nt][1], iz0, by), 0.f);
            float u1x = fmaxf(fmaf(acc[mt][nt][2], iz1, bx), 0.f);
            float u1y = fmaxf(fmaf(acc[mt][nt][3], iz1, by), 0.f);
            *(uint32_t*)(o0 + cc) = pack2(u0x, u0y);
            *(uint32_t*)(o1 + cc) = pack2(u1x, u1y);
        }
    }
}

// ---------------- zero tail of output (mask = all false) ----------------
__global__ void zero_tail_kernel(float* out, long long start, long long total)
{
    long long i = start + (long long)blockIdx.x * blockDim.x + threadIdx.x;
    if (i < total) out[i] = 0.f;
}

// ---------------- launch ----------------
extern "C" void kernel_launch(void* const* d_in, const int* in_sizes, int n_in,
                              void* d_out, int out_size)
{
    const float* ego      = (const float*)d_in[0];
    const float* nbr      = (const float*)d_in[1];
    const float* node_w   = (const float*)d_in[2];
    const float* node_b   = (const float*)d_in[3];
    const float* node_g   = (const float*)d_in[4];
    const float* node_bb  = (const float*)d_in[5];
    const float* ego_w    = (const float*)d_in[6];
    const float* ego_b    = (const float*)d_in[7];
    const float* ego_g    = (const float*)d_in[8];
    const float* ego_bb   = (const float*)d_in[9];
    const float* gat_w    = (const float*)d_in[10];
    const float* gat_asrc = (const float*)d_in[11];
    const float* gat_adst = (const float*)d_in[12];
    const float* gat_b    = (const float*)d_in[13];
    const float* proj_w   = (const float*)d_in[14];
    const float* proj_b   = (const float*)d_in[15];
    float* out = (float*)d_out;

    __half *h0h, *h1h, *whh;
    uint32_t* wpack;
    cudaGetSymbolAddress((void**)&h0h, g_h0h);
    cudaGetSymbolAddress((void**)&h1h, g_h1h);
    cudaGetSymbolAddress((void**)&whh, g_whh);
    cudaGetSymbolAddress((void**)&wpack, g_wpack);

    embed_kernel<<<BATCH * NNODE / 8, 256>>>(ego, nbr, node_w, node_b, node_g, node_bb,
                                             ego_w, ego_b, ego_g, ego_bb);
    adj_kernel<<<dim3(NNODE / 32, 32, BATCH), 256>>>();
    wprep_kernel<<<384, 256>>>(gat_w, proj_w);

    long long hsz = (long long)BATCH * NNODE * DIM;
    if ((long long)out_size > hsz) {
        long long tail = (long long)out_size - hsz;
        int blocks = (int)((tail + 255) / 256);
        zero_tail_kernel<<<blocks, 256>>>(out, hsz, (long long)out_size);
    }

    dim3 ggrid(BATCH * NNODE / 128, 4);
    __half* hbuf[2] = { h0h, h1h };
    for (int l = 0; l < 2; l++) {
        tgemm256<false, true><<<ggrid, 256>>>(
            (const uint32_t*)hbuf[l], wpack + (size_t)l * 32768,
            nullptr, nullptr, whh,
            gat_asrc + l * HEADS * 64, gat_adst + l * HEADS * 64, l);
        gat_attn_mma<<<dim3(4, HEADS, BATCH), 256>>>(whh, gat_b + l * DIM,
                                                     hbuf[1 - l], l);
    }
    tgemm256<true, false><<<ggrid, 256>>>(
        (const uint32_t*)h0h, wpack + 2 * 32768,
        proj_b, out, nullptr, nullptr, nullptr, 0);
}

// round 14
// speedup vs baseline: 2.0239x; 1.0649x over previous
#include <cuda_runtime.h>
#include <cuda_fp16.h>
#include <cstdint>

#define BATCH 16
#define NNODE 1024
#define DIM 256
#define HEADS 4
#define NBR 1023
#define TSTEPS 20

// ---------------- scratch (device globals; no allocation allowed) ----------------
__device__ __half g_h0h[BATCH * NNODE * DIM];
__device__ __half g_h1h[BATCH * NNODE * DIM];
__device__ __half g_whh[BATCH * NNODE * DIM];
__device__ uint32_t g_wpack[3 * 128 * 256];
__device__ float g_pos[BATCH * NNODE * 2];
__device__ float g_as[BATCH * HEADS * NNODE];
__device__ float g_ad[BATCH * HEADS * NNODE];
__device__ uint32_t g_asmaxu[2 * BATCH * HEADS];
__device__ uint32_t g_adjT[BATCH * 32 * NNODE];

// ======================= helpers =======================
__device__ __forceinline__ void mma_f16(float* c, uint32_t a0, uint32_t a1,
                                        uint32_t a2, uint32_t a3,
                                        uint32_t b0, uint32_t b1) {
    asm volatile(
        "mma.sync.aligned.m16n8k16.row.col.f32.f16.f16.f32 "
        "{%0,%1,%2,%3}, {%4,%5,%6,%7}, {%8,%9}, {%0,%1,%2,%3};"
        : "+f"(c[0]), "+f"(c[1]), "+f"(c[2]), "+f"(c[3])
        : "r"(a0), "r"(a1), "r"(a2), "r"(a3), "r"(b0), "r"(b1));
}
__device__ __forceinline__ float slctf(float a, float b, float c) {
    float d;
    asm("slct.f32.f32 %0, %1, %2, %3;" : "=f"(d) : "f"(a), "f"(b), "f"(c));
    return d;
}
__device__ __forceinline__ uint32_t pack2(float lo, float hi) {
    uint32_t d;
    asm("cvt.rn.f16x2.f32 %0, %1, %2;" : "=r"(d) : "f"(hi), "f"(lo));
    return d;
}
__device__ __forceinline__ uint32_t prmtb(uint32_t a, uint32_t b, uint32_t s) {
    uint32_t d;
    asm("prmt.b32 %0, %1, %2, %3;" : "=r"(d) : "r"(a), "r"(b), "r"(s));
    return d;
}
__device__ __forceinline__ uint32_t fenc(float f) {
    uint32_t b = __float_as_uint(f);
    return ((int)b < 0) ? ~b : (b | 0x80000000u);
}
__device__ __forceinline__ float fdec(uint32_t u) {
    return __uint_as_float((u & 0x80000000u) ? (u ^ 0x80000000u) : ~u);
}

// ---------------- weight prep (+output-tail zero) ----------------
__global__ __launch_bounds__(256) void wprep_kernel(
    const float* __restrict__ gat_w, const float* __restrict__ proj_w,
    float* __restrict__ out, long long tstart, long long ttotal)
{
    if (blockIdx.x < 384) {
        int wsel = blockIdx.x >> 7;
        int kp = blockIdx.x & 127;
        int n = threadIdx.x;
        const float* W = (wsel < 2) ? gat_w + (size_t)wsel * 65536 : proj_w;
        float lo = W[(size_t)(2 * kp) * 256 + n];
        float hi = W[(size_t)(2 * kp + 1) * 256 + n];
        g_wpack[(size_t)wsel * 32768 + kp * 256 + n] = pack2(lo, hi);
    } else {
        long long i = tstart + (long long)(blockIdx.x - 384) * 256 + threadIdx.x;
        while (i < ttotal) { out[i] = 0.f; i += 64LL * 256; }
    }
}

// ---------------- embed: 8 nodes per block, fp16 output ----------------
__global__ __launch_bounds__(256) void embed_kernel(
    const float* __restrict__ ego, const float* __restrict__ nbr,
    const float* __restrict__ node_w, const float* __restrict__ node_b,
    const float* __restrict__ node_g, const float* __restrict__ node_bb,
    const float* __restrict__ ego_w, const float* __restrict__ ego_b,
    const float* __restrict__ ego_g, const float* __restrict__ ego_bb)
{
    int t = threadIdx.x;
    int bn0 = blockIdx.x * 8;
    __shared__ float f[8][5];
    __shared__ float ws[8][8], wq[8][8];
    if (t < 40) {
        int nn = t / 5, k = t - nn * 5;
        int bn = bn0 + nn;
        int b = bn >> 10, n = bn & 1023;
        float v = (n == 0) ? ego[(b * TSTEPS + TSTEPS - 1) * 7 + k]
                           : nbr[((b * NBR + (n - 1)) * TSTEPS + TSTEPS - 1) * 11 + k];
        f[nn][k] = v;
        if (k < 2) g_pos[bn * 2 + k] = v;
    }
    __syncthreads();
    float wn[5];
#pragma unroll
    for (int k = 0; k < 5; k++) wn[k] = node_w[k * DIM + t];
    float nb = node_b[t];
    int lane = t & 31, w = t >> 5;
    float vv[8];
#pragma unroll
    for (int nn = 0; nn < 8; nn++) {
        int n = (bn0 + nn) & 1023;
        float v;
        if (n == 0) {
            v = ego_b[t];
#pragma unroll
            for (int k = 0; k < 5; k++) v = fmaf(f[nn][k], ego_w[k * DIM + t], v);
        } else {
            v = nb;
#pragma unroll
            for (int k = 0; k < 5; k++) v = fmaf(f[nn][k], wn[k], v);
        }
        v = fmaxf(v, 0.f);
        vv[nn] = v;
        float s = v, q = v * v;
#pragma unroll
        for (int o = 16; o; o >>= 1) {
            s += __shfl_down_sync(0xffffffffu, s, o);
            q += __shfl_down_sync(0xffffffffu, q, o);
        }
        if (lane == 0) { ws[nn][w] = s; wq[nn][w] = q; }
    }
    __syncthreads();
    float ng = node_g[t], nbb = node_bb[t];
#pragma unroll
    for (int nn = 0; nn < 8; nn++) {
        int bn = bn0 + nn;
        int n = bn & 1023;
        float sum = 0.f, sq = 0.f;
#pragma unroll
        for (int i = 0; i < 8; i++) { sum += ws[nn][i]; sq += wq[nn][i]; }
        float mean = sum * (1.f / 256.f);
        float var = fmaxf(sq * (1.f / 256.f) - mean * mean, 0.f);
        float inv = rsqrtf(var + 1e-5f);
        float gg = ng, bb2 = nbb;
        if (n == 0) { gg = ego_g[t]; bb2 = ego_bb[t]; }
        g_h0h[(size_t)bn * DIM + t] = __float2half_rn((vv[nn] - mean) * inv * gg + bb2);
    }
}

// ---------------- adjacency bitmask + asmax buffer init ----------------
__global__ __launch_bounds__(256) void adj_kernel()
{
    int b = blockIdx.z, jw = blockIdx.y;
    int lane = threadIdx.x & 31, w = threadIdx.x >> 5;
    if (blockIdx.x == 0 && jw == 0 && threadIdx.x < 8) {
        int l = threadIdx.x >> 2, h = threadIdx.x & 3;
        g_asmaxu[l * (BATCH * HEADS) + b * HEADS + h] = 0u;
    }
    int j = jw * 32 + lane;
    float2 pj = ((const float2*)g_pos)[b * NNODE + j];
    int i0 = blockIdx.x * 32 + w;
#pragma unroll
    for (int q = 0; q < 4; q++) {
        int i = i0 + q * 8;
        float2 pi = ((const float2*)g_pos)[b * NNODE + i];
        float dx = pj.x - pi.x, dy = pj.y - pi.y;
        bool a = (fmaf(dx, dx, dy * dy) < 2500.f) || (i == j);
        uint32_t word = __ballot_sync(0xffffffffu, a);
        if (lane == 0) g_adjT[(b * 32 + jw) * NNODE + i] = word;
    }
}

// ---------------- fp16 GEMM 128x128 tile, warp covers one head (SAD in-warp) ----
#define GA_STRIDE 20
#define GBW_STRIDE 136
template <bool BIAS, bool SAD>
__global__ __launch_bounds__(256, 2) void tgemm256(
    const uint32_t* __restrict__ A_pack, const uint32_t* __restrict__ W_pack,
    const float* __restrict__ bias, float* __restrict__ Cf, __half* __restrict__ Ch,
    const float* __restrict__ asrc, const float* __restrict__ adst,
    int sadLayer)
{
    __shared__ uint32_t As_p[128 * GA_STRIDE];
    __shared__ uint32_t Bs_p[16 * GBW_STRIDE];
    int tid = threadIdx.x, w = tid >> 5, lane = tid & 31;
    int g4 = lane >> 2, q4 = lane & 3;
    int m0 = blockIdx.x * 128, n0 = blockIdx.y * 128;
    int wm = w & 3, wn = w >> 2;
    int r0 = wm * 32, c0 = wn * 64;

    int arow = tid >> 2, af4 = tid & 3;
    int brow = tid >> 4, bf4 = tid & 15;
    const uint4* Ag = (const uint4*)(A_pack + (size_t)(m0 + arow) * 128 + af4 * 4);
    const uint32_t* WgBase = W_pack + (size_t)brow * 256 + n0 + bf4 * 4;

    float acc[2][8][4];
#pragma unroll
    for (int mt = 0; mt < 2; mt++)
#pragma unroll
        for (int nt = 0; nt < 8; nt++)
#pragma unroll
            for (int k = 0; k < 4; k++) acc[mt][nt][k] = 0.f;

    uint4 pa0 = Ag[0];
    uint4 pa1 = Ag[(size_t)64 * 32];
    uint4 pb0 = *(const uint4*)WgBase;
    uint4 pb1 = *(const uint4*)(WgBase + 64);

    for (int kc = 0; kc < 8; kc++) {
        __syncthreads();
        *(uint4*)&As_p[arow * GA_STRIDE + af4 * 4] = pa0;
        *(uint4*)&As_p[(arow + 64) * GA_STRIDE + af4 * 4] = pa1;
        *(uint4*)&Bs_p[brow * GBW_STRIDE + bf4 * 4] = pb0;
        *(uint4*)&Bs_p[brow * GBW_STRIDE + 64 + bf4 * 4] = pb1;
        __syncthreads();
        if (kc < 7) {
            const uint4* Agn = (const uint4*)((const uint32_t*)Ag + (kc + 1) * 16);
            const uint32_t* Wgn = WgBase + (size_t)(kc + 1) * 16 * 256;
            pa0 = Agn[0];
            pa1 = Agn[(size_t)64 * 32];
            pb0 = *(const uint4*)Wgn;
            pb1 = *(const uint4*)(Wgn + 64);
        }
#pragma unroll
        for (int kbb = 0; kbb < 2; kbb++) {
            const uint32_t* ap = As_p + (r0 + g4) * GA_STRIDE + kbb * 8 + q4;
            uint32_t a00 = ap[0];
            uint32_t a01 = ap[8 * GA_STRIDE];
            uint32_t a02 = ap[4];
            uint32_t a03 = ap[8 * GA_STRIDE + 4];
            uint32_t a10 = ap[16 * GA_STRIDE];
            uint32_t a11 = ap[24 * GA_STRIDE];
            uint32_t a12 = ap[16 * GA_STRIDE + 4];
            uint32_t a13 = ap[24 * GA_STRIDE + 4];
            const uint32_t* bp = Bs_p + (kbb * 8 + q4) * GBW_STRIDE + c0 + g4;
#pragma unroll
            for (int nt = 0; nt < 8; nt++) {
                uint32_t b0 = bp[nt * 8];
                uint32_t b1 = bp[nt * 8 + 4 * GBW_STRIDE];
                mma_f16(acc[0][nt], a00, a01, a02, a03, b0, b1);
                mma_f16(acc[1][nt], a10, a11, a12, a13, b0, b1);
            }
        }
    }
    // ---- C store ----
#pragma unroll
    for (int mt = 0; mt < 2; mt++) {
        int row = m0 + r0 + mt * 16 + g4;
#pragma unroll
        for (int nt = 0; nt < 8; nt++) {
            int cc = nt * 8 + q4 * 2;
            if (BIAS) {
                float bx = bias[n0 + c0 + cc], by = bias[n0 + c0 + cc + 1];
                float2 u0, u1;
                u0.x = acc[mt][nt][0] + bx; u0.y = acc[mt][nt][1] + by;
                u1.x = acc[mt][nt][2] + bx; u1.y = acc[mt][nt][3] + by;
                *(float2*)&Cf[(size_t)row * 256 + n0 + c0 + cc] = u0;
                *(float2*)&Cf[(size_t)(row + 8) * 256 + n0 + c0 + cc] = u1;
            } else {
                *(uint32_t*)&Ch[(size_t)row * 256 + n0 + c0 + cc] =
                    pack2(acc[mt][nt][0], acc[mt][nt][1]);
                *(uint32_t*)&Ch[(size_t)(row + 8) * 256 + n0 + c0 + cc] =
                    pack2(acc[mt][nt][2], acc[mt][nt][3]);
            }
        }
    }
    // ---- fused a_src / a_dst + asmax: each warp owns head hh, rows r0..r0+31 ----
    if (SAD) {
        int hh = blockIdx.y * 2 + wn;
        int b = m0 >> 10;
        int bh = b * HEADS + hh;
        float as_c[16], ad_c[16];
#pragma unroll
        for (int nt = 0; nt < 8; nt++) {
            int cc = nt * 8 + q4 * 2;
            as_c[nt * 2] = asrc[hh * 64 + cc];
            as_c[nt * 2 + 1] = asrc[hh * 64 + cc + 1];
            ad_c[nt * 2] = adst[hh * 64 + cc];
            ad_c[nt * 2 + 1] = adst[hh * 64 + cc + 1];
        }
        float mloc = -1e30f;
#pragma unroll
        for (int mt = 0; mt < 2; mt++) {
            float sAs = 0.f, sAd = 0.f, sBs = 0.f, sBd = 0.f;
#pragma unroll
            for (int nt = 0; nt < 8; nt++) {
                sAs += acc[mt][nt][0] * as_c[nt * 2] + acc[mt][nt][1] * as_c[nt * 2 + 1];
                sBs += acc[mt][nt][2] * as_c[nt * 2] + acc[mt][nt][3] * as_c[nt * 2 + 1];
                sAd += acc[mt][nt][0] * ad_c[nt * 2] + acc[mt][nt][1] * ad_c[nt * 2 + 1];
                sBd += acc[mt][nt][2] * ad_c[nt * 2] + acc[mt][nt][3] * ad_c[nt * 2 + 1];
            }
#pragma unroll
            for (int o = 1; o < 4; o <<= 1) {
                sAs += __shfl_xor_sync(0xffffffffu, sAs, o);
                sAd += __shfl_xor_sync(0xffffffffu, sAd, o);
                sBs += __shfl_xor_sync(0xffffffffu, sBs, o);
                sBd += __shfl_xor_sync(0xffffffffu, sBd, o);
            }
            int n = (m0 & 1023) + r0 + mt * 16 + g4;
            if (q4 == 0) {
                g_as[bh * NNODE + n] = sAs;
                g_ad[bh * NNODE + n] = sAd;
                g_as[bh * NNODE + n + 8] = sBs;
                g_ad[bh * NNODE + n + 8] = sBd;
            }
            mloc = fmaxf(mloc, fmaxf(sAs, sBs));
        }
#pragma unroll
        for (int o = 16; o; o >>= 1)
            mloc = fmaxf(mloc, __shfl_xor_sync(0xffffffffu, mloc, o));
        if (lane == 0)
            atomicMax(&g_asmaxu[sadLayer * (BATCH * HEADS) + bh], fenc(mloc));
    }
}

// ---------------- GAT attention: fp16 m16n8k16 MMA, fp16 wh input ----
#define VP_STRIDE 72
__global__ __launch_bounds__(256, 2) void gat_attn_mma(
    const __half* __restrict__ whh, const float* __restrict__ gbias,
    __half* __restrict__ hout, int layer)
{
    __shared__ uint32_t v_p[32 * VP_STRIDE];
    __shared__ float4 je[64];
    __shared__ uint32_t adj_sm[512];

    int tid = threadIdx.x, w = tid >> 5, lane = tid & 31;
    int g4 = lane >> 2, q4 = lane & 3;
    int it = blockIdx.x, hh = blockIdx.y, b = blockIdx.z;
    int i0 = it * 256, bh = b * HEADS + hh;
    int r0 = w * 32;

    float F1[4], F2[4], adreg[4];
    {
        float mx = fdec(g_asmaxu[layer * (BATCH * HEADS) + bh]);
#pragma unroll
        for (int t = 0; t < 4; t++) {
            float ad = g_ad[bh * NNODE + i0 + r0 + t * 8 + g4];
            adreg[t] = ad;
            float mm = mx + ad;
            float mr = fmaxf(mm, 0.2f * mm);
            F1[t] = __expf(ad - mr);
            F2[t] = __expf(0.2f * ad - mr);
        }
    }
    {
        int jp = tid >> 3, cc = 64 + (tid & 7);
        v_p[jp * VP_STRIDE + cc] = (cc == 64) ? 0x3C003C00u : 0u;
    }

    float acc[2][9][4];
#pragma unroll
    for (int mt = 0; mt < 2; mt++)
#pragma unroll
        for (int n = 0; n < 9; n++)
#pragma unroll
            for (int k = 0; k < 4; k++) acc[mt][n][k] = 0.f;

    const __half* whb = whh + ((size_t)(b * NNODE)) * DIM + hh * 64;
    const uint32_t* adjb = g_adjT + (size_t)b * 32 * NNODE + i0;

    for (int ch = 0; ch < 16; ch++) {
        int j0c = ch * 64;
        __syncthreads();
        {
            int jp = tid >> 3, cb = (tid & 7) * 8;
            const uint4* rA = (const uint4*)(whb + (size_t)(j0c + 2 * jp) * DIM + cb);
            const uint4* rB = (const uint4*)(whb + (size_t)(j0c + 2 * jp + 1) * DIM + cb);
            uint4 a = rA[0], bb4 = rB[0];
            uint4 o0, o1;
            o0.x = prmtb(a.x, bb4.x, 0x5410); o0.y = prmtb(a.x, bb4.x, 0x7632);
            o0.z = prmtb(a.y, bb4.y, 0x5410); o0.w = prmtb(a.y, bb4.y, 0x7632);
            o1.x = prmtb(a.z, bb4.z, 0x5410); o1.y = prmtb(a.z, bb4.z, 0x7632);
            o1.z = prmtb(a.w, bb4.w, 0x5410); o1.w = prmtb(a.w, bb4.w, 0x7632);
            *(uint4*)&v_p[jp * VP_STRIDE + cb] = o0;
            *(uint4*)&v_p[jp * VP_STRIDE + cb + 4] = o1;
        }
        if (tid < 64) {
            float a = g_as[bh * NNODE + j0c + tid];
            je[tid] = make_float4(a, __expf(a), __expf(0.2f * a), 0.f);
        }
        adj_sm[tid] = adjb[(size_t)(2 * ch) * NNODE + tid];
        adj_sm[256 + tid] = adjb[(size_t)(2 * ch + 1) * NNODE + tid];
        __syncthreads();
        uint32_t Aw[2][4];
#pragma unroll
        for (int t = 0; t < 4; t++) {
            Aw[0][t] = adj_sm[r0 + t * 8 + g4];
            Aw[1][t] = adj_sm[256 + r0 + t * 8 + g4];
        }
        uint32_t andall = Aw[0][0] & Aw[0][1] & Aw[0][2] & Aw[0][3]
                        & Aw[1][0] & Aw[1][1] & Aw[1][2] & Aw[1][3];
        bool allones = __all_sync(0xffffffffu, andall == 0xffffffffu);

#pragma unroll
        for (int kb = 0; kb < 4; kb++) {
            int jlo = kb * 16 + 2 * q4;
            float4 jeA = je[jlo];
            float4 jeB = je[jlo + 1];
            float4 jeC = je[jlo + 8];
            float4 jeD = je[jlo + 9];
            uint32_t afr[2][4];
            if (allones) {
#pragma unroll
                for (int t = 0; t < 4; t++) {
                    float pa = slctf(jeA.y * F1[t], jeA.z * F2[t], jeA.x + adreg[t]);
                    float pb = slctf(jeB.y * F1[t], jeB.z * F2[t], jeB.x + adreg[t]);
                    float pc = slctf(jeC.y * F1[t], jeC.z * F2[t], jeC.x + adreg[t]);
                    float pd = slctf(jeD.y * F1[t], jeD.z * F2[t], jeD.x + adreg[t]);
                    afr[t >> 1][t & 1] = pack2(pa, pb);
                    afr[t >> 1][2 + (t & 1)] = pack2(pc, pd);
                }
            } else {
                int half = kb >> 1;
                int s = jlo & 31;
#pragma unroll
                for (int t = 0; t < 4; t++) {
                    uint32_t wv = Aw[half][t];
                    uint32_t b2lo = (wv >> s) & 3u;
                    uint32_t b2hi = (wv >> (s + 8)) & 3u;
                    uint32_t mlo = ((b2lo & 1u) ? 0x0000FFFFu : 0u) |
                                   ((b2lo & 2u) ? 0xFFFF0000u : 0u);
                    uint32_t mhi = ((b2hi & 1u) ? 0x0000FFFFu : 0u) |
                                   ((b2hi & 2u) ? 0xFFFF0000u : 0u);
                    float pa = slctf(jeA.y * F1[t], jeA.z * F2[t], jeA.x + adreg[t]);
                    float pb = slctf(jeB.y * F1[t], jeB.z * F2[t], jeB.x + adreg[t]);
                    float pc = slctf(jeC.y * F1[t], jeC.z * F2[t], jeC.x + adreg[t]);
                    float pd = slctf(jeD.y * F1[t], jeD.z * F2[t], jeD.x + adreg[t]);
                    afr[t >> 1][t & 1] = pack2(pa, pb) & mlo;
                    afr[t >> 1][2 + (t & 1)] = pack2(pc, pd) & mhi;
                }
            }
            const uint32_t* bp = v_p + (kb * 8 + q4) * VP_STRIDE + g4;
#pragma unroll
            for (int nt = 0; nt < 9; nt++) {
                uint32_t b0 = bp[nt * 8];
                uint32_t b1 = bp[nt * 8 + 4 * VP_STRIDE];
                mma_f16(acc[0][nt], afr[0][0], afr[0][1], afr[0][2], afr[0][3], b0, b1);
                mma_f16(acc[1][nt], afr[1][0], afr[1][1], afr[1][2], afr[1][3], b0, b1);
            }
        }
    }
    const float* bp = gbias + hh * 64;
#pragma unroll
    for (int mt = 0; mt < 2; mt++) {
        float z0 = __shfl_sync(0xffffffffu, acc[mt][8][0], lane & 28);
        float z1 = __shfl_sync(0xffffffffu, acc[mt][8][2], lane & 28);
        float iz0 = 1.f / z0;
        float iz1 = 1.f / z1;
        int rowg = i0 + r0 + mt * 16 + g4;
        __half* o0 = hout + ((size_t)(b * NNODE) + rowg) * DIM + hh * 64;
        __half* o1 = o0 + 8 * DIM;
#pragma unroll
        for (int nt = 0; nt < 8; nt++) {
            int cc = nt * 8 + q4 * 2;
            float bx = bp[cc], by = bp[cc + 1];
            float u0x = fmaxf(fmaf(acc[mt][nt][0], iz0, bx), 0.f);
            float u0y = fmaxf(fmaf(acc[mt][nt][1], iz0, by), 0.f);
            float u1x = fmaxf(fmaf(acc[mt][nt][2], iz1, bx), 0.f);
            float u1y = fmaxf(fmaf(acc[mt][nt][3], iz1, by), 0.f);
            *(uint32_t*)(o0 + cc) = pack2(u0x, u0y);
            *(uint32_t*)(o1 + cc) = pack2(u1x, u1y);
        }
    }
}

// ---------------- launch ----------------
extern "C" void kernel_launch(void* const* d_in, const int* in_sizes, int n_in,
                              void* d_out, int out_size)
{
    const float* ego      = (const float*)d_in[0];
    const float* nbr      = (const float*)d_in[1];
    const float* node_w   = (const float*)d_in[2];
    const float* node_b   = (const float*)d_in[3];
    const float* node_g   = (const float*)d_in[4];
    const float* node_bb  = (const float*)d_in[5];
    const float* ego_w    = (const float*)d_in[6];
    const float* ego_b    = (const float*)d_in[7];
    const float* ego_g    = (const float*)d_in[8];
    const float* ego_bb   = (const float*)d_in[9];
    const float* gat_w    = (const float*)d_in[10];
    const float* gat_asrc = (const float*)d_in[11];
    const float* gat_adst = (const float*)d_in[12];
    const float* gat_b    = (const float*)d_in[13];
    const float* proj_w   = (const float*)d_in[14];
    const float* proj_b   = (const float*)d_in[15];
    float* out = (float*)d_out;

    __half *h0h, *h1h, *whh;
    uint32_t* wpack;
    cudaGetSymbolAddress((void**)&h0h, g_h0h);
    cudaGetSymbolAddress((void**)&h1h, g_h1h);
    cudaGetSymbolAddress((void**)&whh, g_whh);
    cudaGetSymbolAddress((void**)&wpack, g_wpack);

    long long hsz = (long long)BATCH * NNODE * DIM;

    embed_kernel<<<BATCH * NNODE / 8, 256>>>(ego, nbr, node_w, node_b, node_g, node_bb,
                                             ego_w, ego_b, ego_g, ego_bb);
    adj_kernel<<<dim3(NNODE / 32, 32, BATCH), 256>>>();
    wprep_kernel<<<448, 256>>>(gat_w, proj_w, out, hsz, (long long)out_size);

    dim3 ggrid(BATCH * NNODE / 128, 2);
    __half* hbuf[2] = { h0h, h1h };
    for (int l = 0; l < 2; l++) {
        tgemm256<false, true><<<ggrid, 256>>>(
            (const uint32_t*)hbuf[l], wpack + (size_t)l * 32768,
            nullptr, nullptr, whh,
            gat_asrc + l * HEADS * 64, gat_adst + l * HEADS * 64, l);
        gat_attn_mma<<<dim3(4, HEADS, BATCH), 256>>>(whh, gat_b + l * DIM,
                                                     hbuf[1 - l], l);
    }
    tgemm256<true, false><<<ggrid, 256>>>(
        (const uint32_t*)h0h, wpack + 2 * 32768,
        proj_b, out, nullptr, nullptr, nullptr, 0);
}